// round 5
// baseline (speedup 1.0000x reference)
#include <cuda_runtime.h>
#include <math.h>

#define NNODES 50000
#define LDIM   4
#define DDIM   128
#define KDIM   16
#define EEDGES 800000
#define MROWS  (LDIM * NNODES)        // 200000
#define DECAYF 0.7f
#define EPSF   1e-5f

// ---------------- scratch (device globals; no allocation) ----------------
__device__ float g_proj[MROWS * DDIM];
__device__ float g_v   [MROWS * DDIM];
__device__ float g_agg [MROWS * DDIM];
__device__ float g_sage[MROWS * DDIM];
__device__ float g_att [MROWS * DDIM];
__device__ float g_h   [MROWS * DDIM];
__device__ float g_w0 [MROWS];
__device__ float g_it1[MROWS];
__device__ float g_it2[MROWS];
__device__ float g_bt [6 * DDIM * DDIM];   // transposed weights

// CSR build scratch
__device__ int   g_cnt[NNODES];
__device__ int   g_cur[NNODES];
__device__ int   g_rowstart[NNODES + 1];
__device__ int   g_ecol[EEDGES];
__device__ float g_eval[EEDGES];

// ================= weight transpose (once per launch, tiny) =================
struct SixPtr { const float* p[6]; };

// dst[m][n][k] = src_m[k*128 + n]; each src is a 128x128 block
__global__ void transpose_kernel(SixPtr srcs, float* __restrict__ dst)
{
    __shared__ float tile[32][33];
    const int m = blockIdx.z;
    const float* src = srcs.p[m];
    float* d = dst + m * DDIM * DDIM;
    const int bx = blockIdx.x * 32;   // n tile
    const int by = blockIdx.y * 32;   // k tile
    const int tx = threadIdx.x, ty = threadIdx.y;
#pragma unroll
    for (int j = 0; j < 32; j += 8)
        tile[ty + j][tx] = src[(by + ty + j) * DDIM + bx + tx];
    __syncthreads();
#pragma unroll
    for (int j = 0; j < 32; j += 8)
        d[(bx + ty + j) * DDIM + by + tx] = tile[tx][ty + j];
}

// ================= CSR construction =================
__global__ void hist_kernel(const int* __restrict__ ei, int* __restrict__ cnt)
{
    int e = blockIdx.x * blockDim.x + threadIdx.x;
    if (e < EEDGES) atomicAdd(&cnt[ei[e]], 1);
}

__global__ void scan_kernel(const int* __restrict__ cnt, int* __restrict__ rowstart)
{
    const int T = 1024;
    __shared__ int partial[T];
    const int tid = threadIdx.x;
    const int chunk = (NNODES + T - 1) / T;
    const int base = tid * chunk;
    int s = 0;
    for (int i = 0; i < chunk; i++) {
        int idx = base + i;
        if (idx < NNODES) s += cnt[idx];
    }
    partial[tid] = s;
    __syncthreads();
    for (int off = 1; off < T; off <<= 1) {
        int v = (tid >= off) ? partial[tid - off] : 0;
        __syncthreads();
        partial[tid] += v;
        __syncthreads();
    }
    int run = (tid == 0) ? 0 : partial[tid - 1];
    for (int i = 0; i < chunk; i++) {
        int idx = base + i;
        if (idx < NNODES) { rowstart[idx] = run; run += cnt[idx]; }
    }
    if (tid == T - 1) rowstart[NNODES] = run;
}

__global__ void scatter_kernel(const int* __restrict__ ei, const float* __restrict__ ev,
                               const int* __restrict__ rowstart, int* __restrict__ cur,
                               int* __restrict__ ecol, float* __restrict__ eval_)
{
    int e = blockIdx.x * blockDim.x + threadIdx.x;
    if (e >= EEDGES) return;
    const int r = ei[e];
    const int pos = rowstart[r] + atomicAdd(&cur[r], 1);
    ecol[pos]  = ei[EEDGES + e];
    eval_[pos] = ev[e];
}

// ================= gather spmm: warp per row, all 4 L slices =================
__global__ void __launch_bounds__(256) spmm_gather(
    const int* __restrict__ rowstart,
    const int* __restrict__ ecol, const float* __restrict__ eval_,
    const float* __restrict__ x, float* __restrict__ agg)
{
    const int row = (blockIdx.x * blockDim.x + threadIdx.x) >> 5;
    const int lane = threadIdx.x & 31;
    if (row >= NNODES) return;

    const int s = rowstart[row];
    const int e = rowstart[row + 1];
    const float4* x4 = (const float4*)x;

    float4 a0 = make_float4(0.f, 0.f, 0.f, 0.f);
    float4 a1 = a0, a2 = a0, a3 = a0;
    for (int i = s; i < e; i++) {
        const int c = ecol[i];
        const float v = eval_[i];
        float4 t0 = x4[((size_t)c) * 32 + lane];
        float4 t1 = x4[((size_t)NNODES + c) * 32 + lane];
        float4 t2 = x4[((size_t)2 * NNODES + c) * 32 + lane];
        float4 t3 = x4[((size_t)3 * NNODES + c) * 32 + lane];
        a0.x += v * t0.x; a0.y += v * t0.y; a0.z += v * t0.z; a0.w += v * t0.w;
        a1.x += v * t1.x; a1.y += v * t1.y; a1.z += v * t1.z; a1.w += v * t1.w;
        a2.x += v * t2.x; a2.y += v * t2.y; a2.z += v * t2.z; a2.w += v * t2.w;
        a3.x += v * t3.x; a3.y += v * t3.y; a3.z += v * t3.z; a3.w += v * t3.w;
    }
    float4* o = (float4*)agg;
    o[((size_t)row) * 32 + lane]              = a0;
    o[((size_t)NNODES + row) * 32 + lane]     = a1;
    o[((size_t)2 * NNODES + row) * 32 + lane] = a2;
    o[((size_t)3 * NNODES + row) * 32 + lane] = a3;
}

// ================= retention spmm on [L,N] weights (gather) =================
__global__ void __launch_bounds__(256) ret_gather(
    const int* __restrict__ rowstart,
    const int* __restrict__ ecol, const float* __restrict__ eval_,
    const float* __restrict__ src, float* __restrict__ dst)
{
    const int row = (blockIdx.x * blockDim.x + threadIdx.x) >> 5;
    const int lane = threadIdx.x & 31;
    if (row >= NNODES) return;
    const int s = rowstart[row];
    const int e = rowstart[row + 1];

    float a0 = 0.f, a1 = 0.f, a2 = 0.f, a3 = 0.f;
    for (int i = s + lane; i < e; i += 32) {
        const int c = ecol[i];
        const float v = DECAYF * eval_[i];
        a0 += v * src[c];
        a1 += v * src[NNODES + c];
        a2 += v * src[2 * NNODES + c];
        a3 += v * src[3 * NNODES + c];
    }
#pragma unroll
    for (int off = 16; off; off >>= 1) {
        a0 += __shfl_xor_sync(0xFFFFFFFFu, a0, off);
        a1 += __shfl_xor_sync(0xFFFFFFFFu, a1, off);
        a2 += __shfl_xor_sync(0xFFFFFFFFu, a2, off);
        a3 += __shfl_xor_sync(0xFFFFFFFFu, a3, off);
    }
    if (lane == 0) {
        dst[row]              = a0;
        dst[NNODES + row]     = a1;
        dst[2 * NNODES + row] = a2;
        dst[3 * NNODES + row] = a3;
    }
}

// ================= tf32 tensor-core GEMM (ldmatrix + 128x128 block) =========
// C[M,128] = A[M, NCHUNK*128] @ B (B given pre-transposed as Bt[n][k]).
// Block: 128 rows x 128 cols, 8 warps. Warp (wr,wc): rows wr*32..+31, cols wc*64..+63.
#define AST 132
#define BST 132
#define GEMM_SMEM ((128 * AST + 128 * BST) * 4)   // 135168 bytes

__device__ __forceinline__ unsigned f2tf(float f)
{
    unsigned u;
    asm("cvt.rna.tf32.f32 %0, %1;" : "=r"(u) : "f"(f));
    return u;
}

__device__ __forceinline__ void mma8(float* c, const unsigned* a, unsigned b0, unsigned b1)
{
    asm volatile(
        "mma.sync.aligned.m16n8k8.row.col.f32.tf32.tf32.f32 "
        "{%0,%1,%2,%3},{%4,%5,%6,%7},{%8,%9},{%0,%1,%2,%3};"
        : "+f"(c[0]), "+f"(c[1]), "+f"(c[2]), "+f"(c[3])
        : "r"(a[0]), "r"(a[1]), "r"(a[2]), "r"(a[3]), "r"(b0), "r"(b1));
}

#define LDSM4(r, addr) \
    asm volatile("ldmatrix.sync.aligned.m8n8.x4.shared.b16 {%0,%1,%2,%3}, [%4];" \
        : "=r"((r)[0]), "=r"((r)[1]), "=r"((r)[2]), "=r"((r)[3]) : "r"(addr))

template <int NCHUNK, int EPI>
__global__ void __launch_bounds__(256, 1) gemm_tc(
    const float* __restrict__ A0, const float* __restrict__ A1,
    const float* __restrict__ Bt,
    const float* __restrict__ bias, const float* __restrict__ addb,
    const float* __restrict__ lng, const float* __restrict__ lnb,
    float* __restrict__ C)
{
    extern __shared__ unsigned smem_u[];
    unsigned* As = smem_u;             // 128 x AST tf32
    unsigned* Bs = smem_u + 128 * AST; // 128 x BST tf32
    float* Cs = (float*)smem_u;        // epilogue staging (128 x AST floats)

    const int tid  = threadIdx.x;
    const int lane = tid & 31;
    const int wid  = tid >> 5;
    const int wr   = wid & 3;    // m quadrant (rows wr*32)
    const int wc   = wid >> 2;   // n half (cols wc*64)
    const int tg   = lane & 3;
    const int gr   = lane >> 2;
    const int blockRow = blockIdx.x * 128;

    // ldmatrix per-thread base addresses (bytes, shared space)
    const unsigned sbase = (unsigned)__cvta_generic_to_shared(smem_u);
    const unsigned aAddr = sbase +
        ((wr * 32 + (lane & 15)) * AST + (lane >> 4) * 4) * 4u;
    const unsigned bAddr = sbase + 128u * AST * 4u +
        ((wc * 64 + (lane >> 4) * 8 + (lane & 7)) * BST + ((lane >> 3) & 1) * 4) * 4u;

    float acc[2][8][4];
#pragma unroll
    for (int mt = 0; mt < 2; mt++)
#pragma unroll
        for (int nt = 0; nt < 8; nt++)
#pragma unroll
            for (int j = 0; j < 4; j++) acc[mt][nt][j] = 0.f;

#pragma unroll
    for (int ch = 0; ch < NCHUNK; ch++) {
        const float* A = (NCHUNK == 2 && ch == 1) ? A1 : A0;
        // A tile: rows blockRow..+127 (clamp), 128 k
        const float4* Ag = (const float4*)A;
#pragma unroll
        for (int f = 0; f < 16; f++) {
            int i4 = tid + f * 256;                 // 0..4095
            int r = i4 >> 5;
            int g = i4 & 31;
            int grow = blockRow + r;
            if (grow >= MROWS) grow = MROWS - 1;    // clamp (never stored)
            float4 v = Ag[(size_t)grow * 32 + g];
            uint4 t = make_uint4(f2tf(v.x), f2tf(v.y), f2tf(v.z), f2tf(v.w));
            *(uint4*)(As + r * AST + g * 4) = t;
        }
        // B tile: Bt chunk [128][128] contiguous
        const float4* Bg = (const float4*)(Bt + ch * DDIM * DDIM);
#pragma unroll
        for (int f = 0; f < 16; f++) {
            int i4 = tid + f * 256;
            int r = i4 >> 5;
            int g = i4 & 31;
            float4 v = Bg[i4];
            uint4 t = make_uint4(f2tf(v.x), f2tf(v.y), f2tf(v.z), f2tf(v.w));
            *(uint4*)(Bs + r * BST + g * 4) = t;
        }
        __syncthreads();

#pragma unroll
        for (int k8 = 0; k8 < 16; k8++) {
            const unsigned ko = k8 * 32;   // 8 floats = 32 bytes
            unsigned af0[4], af1[4], bf[4][4];
            LDSM4(af0, aAddr + ko);
            LDSM4(af1, aAddr + 16 * AST * 4 + ko);
            LDSM4(bf[0], bAddr + ko);
            LDSM4(bf[1], bAddr + 16 * BST * 4 + ko);
            LDSM4(bf[2], bAddr + 32 * BST * 4 + ko);
            LDSM4(bf[3], bAddr + 48 * BST * 4 + ko);
#pragma unroll
            for (int nt = 0; nt < 8; nt++) {
                const unsigned b0 = bf[nt >> 1][(nt & 1) * 2];
                const unsigned b1 = bf[nt >> 1][(nt & 1) * 2 + 1];
                mma8(acc[0][nt], af0, b0, b1);
                mma8(acc[1][nt], af1, b0, b1);
            }
        }
        __syncthreads();
    }

    // stage accumulators to smem
#pragma unroll
    for (int mt = 0; mt < 2; mt++) {
        const int r0 = wr * 32 + mt * 16 + gr;
#pragma unroll
        for (int nt = 0; nt < 8; nt++) {
            const int c = wc * 64 + nt * 8 + 2 * tg;
            *(float2*)(Cs + r0 * AST + c)       = make_float2(acc[mt][nt][0], acc[mt][nt][1]);
            *(float2*)(Cs + (r0 + 8) * AST + c) = make_float2(acc[mt][nt][2], acc[mt][nt][3]);
        }
    }
    __syncthreads();

    // epilogue: warp wid owns rows wid*16..+15; lane owns 4 cols
    float4 bias4 = make_float4(0.f, 0.f, 0.f, 0.f);
    if (EPI >= 1 && bias) bias4 = ((const float4*)bias)[lane];

    if constexpr (EPI == 2) {
        const float4 g4 = ((const float4*)lng)[lane];
        const float4 b4 = ((const float4*)lnb)[lane];
#pragma unroll
        for (int i = 0; i < 16; i++) {
            const int r = wid * 16 + i;
            const size_t gr_ = (size_t)blockRow + r;
            if (gr_ >= MROWS) break;
            float4 t = *(const float4*)(Cs + r * AST + lane * 4);
            t.x += bias4.x; t.y += bias4.y; t.z += bias4.z; t.w += bias4.w;
            if (addb) {
                float4 ad = ((const float4*)addb)[gr_ * 32 + lane];
                t.x += ad.x; t.y += ad.y; t.z += ad.z; t.w += ad.w;
            }
            float4 s;
            s.x = t.x / (1.f + expf(-t.x));
            s.y = t.y / (1.f + expf(-t.y));
            s.z = t.z / (1.f + expf(-t.z));
            s.w = t.w / (1.f + expf(-t.w));
            float sum = s.x + s.y + s.z + s.w;
            float sq  = s.x * s.x + s.y * s.y + s.z * s.z + s.w * s.w;
#pragma unroll
            for (int off = 16; off; off >>= 1) {
                sum += __shfl_xor_sync(0xFFFFFFFFu, sum, off);
                sq  += __shfl_xor_sync(0xFFFFFFFFu, sq,  off);
            }
            const float mean = sum * (1.f / 128.f);
            const float var  = sq * (1.f / 128.f) - mean * mean;
            const float rstd = rsqrtf(var + EPSF);
            float4 o;
            o.x = (s.x - mean) * rstd * g4.x + b4.x;
            o.y = (s.y - mean) * rstd * g4.y + b4.y;
            o.z = (s.z - mean) * rstd * g4.z + b4.z;
            o.w = (s.w - mean) * rstd * g4.w + b4.w;
            ((float4*)C)[gr_ * 32 + lane] = o;
        }
    } else {
#pragma unroll
        for (int i = 0; i < 16; i++) {
            const int r = wid * 16 + i;
            const size_t gr_ = (size_t)blockRow + r;
            if (gr_ >= MROWS) break;
            float4 t = *(const float4*)(Cs + r * AST + lane * 4);
            t.x += bias4.x; t.y += bias4.y; t.z += bias4.z; t.w += bias4.w;
            ((float4*)C)[gr_ * 32 + lane] = t;
        }
    }
}

// ---------------- k/q retention weights ----------------
__global__ void kq_kernel(const float* __restrict__ x,
                          const float* __restrict__ Wk, const float* __restrict__ Wq,
                          float* __restrict__ w0)
{
    __shared__ float4 sk4[KDIM * 32];
    __shared__ float4 sq4[KDIM * 32];
    float* sk = (float*)sk4;
    float* sqm = (float*)sq4;
    for (int idx = threadIdx.x; idx < DDIM * KDIM; idx += blockDim.x) {
        int k = idx >> 4, j = idx & 15;
        sk[j * DDIM + k] = Wk[idx];
        sqm[j * DDIM + k] = Wq[idx];
    }
    __syncthreads();

    const int lane = threadIdx.x & 31;
    int warp = (blockIdx.x * blockDim.x + threadIdx.x) >> 5;
    const int nwarps = (gridDim.x * blockDim.x) >> 5;

    for (size_t r = warp; r < (size_t)MROWS; r += nwarps) {
        const float4 xv = ((const float4*)x)[r * 32 + lane];
        float pk[KDIM], pq[KDIM];
#pragma unroll
        for (int j = 0; j < KDIM; j++) {
            float4 wk = sk4[j * 32 + lane];
            float4 wq = sq4[j * 32 + lane];
            pk[j] = xv.x * wk.x + xv.y * wk.y + xv.z * wk.z + xv.w * wk.w;
            pq[j] = xv.x * wq.x + xv.y * wq.y + xv.z * wq.z + xv.w * wq.w;
        }
#pragma unroll
        for (int off = 16; off; off >>= 1) {
#pragma unroll
            for (int j = 0; j < KDIM; j++) {
                pk[j] += __shfl_xor_sync(0xFFFFFFFFu, pk[j], off);
                pq[j] += __shfl_xor_sync(0xFFFFFFFFu, pq[j], off);
            }
        }
        if (lane == 0) {
            float s = 0.f;
#pragma unroll
            for (int j = 0; j < KDIM; j++) s += pk[j] * pq[j];
            w0[r] = s * (1.f / (float)KDIM);
        }
    }
}

// ---------------- attention output: att = LN(v * (w0+it1+it2)) ----------------
__global__ void att_ln_kernel(const float* __restrict__ v,
                              const float* __restrict__ w0, const float* __restrict__ it1,
                              const float* __restrict__ it2,
                              const float* __restrict__ g, const float* __restrict__ b,
                              float* __restrict__ out)
{
    const int lane = threadIdx.x & 31;
    int warp = (blockIdx.x * blockDim.x + threadIdx.x) >> 5;
    const int nwarps = (gridDim.x * blockDim.x) >> 5;
    const float4 g4 = ((const float4*)g)[lane];
    const float4 b4 = ((const float4*)b)[lane];

    for (size_t r = warp; r < (size_t)MROWS; r += nwarps) {
        const float w = w0[r] + it1[r] + it2[r];
        float4 s = ((const float4*)v)[r * 32 + lane];
        s.x *= w; s.y *= w; s.z *= w; s.w *= w;
        float sum = s.x + s.y + s.z + s.w;
        float sq  = s.x * s.x + s.y * s.y + s.z * s.z + s.w * s.w;
#pragma unroll
        for (int off = 16; off; off >>= 1) {
            sum += __shfl_xor_sync(0xFFFFFFFFu, sum, off);
            sq  += __shfl_xor_sync(0xFFFFFFFFu, sq,  off);
        }
        const float mean = sum * (1.f / 128.f);
        const float var  = sq * (1.f / 128.f) - mean * mean;
        const float rstd = rsqrtf(var + EPSF);
        float4 o;
        o.x = (s.x - mean) * rstd * g4.x + b4.x;
        o.y = (s.y - mean) * rstd * g4.y + b4.y;
        o.z = (s.z - mean) * rstd * g4.z + b4.z;
        o.w = (s.w - mean) * rstd * g4.w + b4.w;
        ((float4*)out)[r * 32 + lane] = o;
    }
}

// ---------------- host ----------------
extern "C" void kernel_launch(void* const* d_in, const int* in_sizes, int n_in,
                              void* d_out, int out_size)
{
    const float* x          = (const float*)d_in[0];
    const int*   ei         = (const int*)  d_in[1];
    const float* ev         = (const float*)d_in[2];
    const float* sage_W     = (const float*)d_in[3];
    const float* sage_b     = (const float*)d_in[4];
    const float* sage_aggW  = (const float*)d_in[5];
    const float* sage_ln_g  = (const float*)d_in[6];
    const float* sage_ln_b  = (const float*)d_in[7];
    const float* att_Wk     = (const float*)d_in[8];
    const float* att_Wq     = (const float*)d_in[9];
    const float* att_Wv     = (const float*)d_in[10];
    const float* att_ln_g   = (const float*)d_in[11];
    const float* att_ln_b   = (const float*)d_in[12];
    const float* lin1_W     = (const float*)d_in[13];
    const float* lin1_b     = (const float*)d_in[14];
    const float* lin2_W     = (const float*)d_in[15];
    const float* lin2_b     = (const float*)d_in[16];
    const float* ln1_g      = (const float*)d_in[17];
    const float* ln1_b      = (const float*)d_in[18];
    const float* ln2_g      = (const float*)d_in[19];
    const float* ln2_b      = (const float*)d_in[20];
    float* out = (float*)d_out;

    float *proj, *v, *agg, *sage, *att, *h, *w0, *it1, *it2, *bt;
    cudaGetSymbolAddress((void**)&proj, g_proj);
    cudaGetSymbolAddress((void**)&v,    g_v);
    cudaGetSymbolAddress((void**)&agg,  g_agg);
    cudaGetSymbolAddress((void**)&sage, g_sage);
    cudaGetSymbolAddress((void**)&att,  g_att);
    cudaGetSymbolAddress((void**)&h,    g_h);
    cudaGetSymbolAddress((void**)&w0,   g_w0);
    cudaGetSymbolAddress((void**)&it1,  g_it1);
    cudaGetSymbolAddress((void**)&it2,  g_it2);
    cudaGetSymbolAddress((void**)&bt,   g_bt);

    int *cnt, *cur, *rowstart, *ecol;
    float *eval_;
    cudaGetSymbolAddress((void**)&cnt,      g_cnt);
    cudaGetSymbolAddress((void**)&cur,      g_cur);
    cudaGetSymbolAddress((void**)&rowstart, g_rowstart);
    cudaGetSymbolAddress((void**)&ecol,     g_ecol);
    cudaGetSymbolAddress((void**)&eval_,    g_eval);

    cudaFuncSetAttribute(gemm_tc<1, 0>, cudaFuncAttributeMaxDynamicSharedMemorySize, GEMM_SMEM);
    cudaFuncSetAttribute(gemm_tc<1, 1>, cudaFuncAttributeMaxDynamicSharedMemorySize, GEMM_SMEM);
    cudaFuncSetAttribute(gemm_tc<1, 2>, cudaFuncAttributeMaxDynamicSharedMemorySize, GEMM_SMEM);
    cudaFuncSetAttribute(gemm_tc<2, 2>, cudaFuncAttributeMaxDynamicSharedMemorySize, GEMM_SMEM);

    const int gemmGrid = (MROWS + 127) / 128;  // 1563

    // ---- weight transposes: [0]=sage_W [1]=att_Wv [2]=sage_aggW [3,4]=lin1 [5]=lin2 ----
    SixPtr sp;
    sp.p[0] = sage_W; sp.p[1] = att_Wv; sp.p[2] = sage_aggW;
    sp.p[3] = lin1_W; sp.p[4] = lin1_W + DDIM * DDIM; sp.p[5] = lin2_W;
    {
        dim3 tg(4, 4, 6), tb(32, 8);
        transpose_kernel<<<tg, tb>>>(sp, bt);
    }

    // ---- CSR build ----
    cudaMemsetAsync(cnt, 0, NNODES * sizeof(int), 0);
    cudaMemsetAsync(cur, 0, NNODES * sizeof(int), 0);
    hist_kernel<<<(EEDGES + 255) / 256, 256>>>(ei, cnt);
    scan_kernel<<<1, 1024>>>(cnt, rowstart);
    scatter_kernel<<<(EEDGES + 255) / 256, 256>>>(ei, ev, rowstart, cur, ecol, eval_);

    // proj = x @ sage_W + sage_b ; v = x @ att_Wv
    gemm_tc<1, 1><<<gemmGrid, 256, GEMM_SMEM>>>(x, nullptr, bt + 0 * DDIM * DDIM,
                                                sage_b, nullptr, nullptr, nullptr, proj);
    gemm_tc<1, 0><<<gemmGrid, 256, GEMM_SMEM>>>(x, nullptr, bt + 1 * DDIM * DDIM,
                                                nullptr, nullptr, nullptr, nullptr, v);

    // retention base weights
    kq_kernel<<<1480, 256>>>(x, att_Wk, att_Wq, w0);

    // graph aggregation: gather, warp per row (all 4 L)
    spmm_gather<<<(NNODES * 32 + 255) / 256, 256>>>(rowstart, ecol, eval_, x, agg);

    // retention iterations
    ret_gather<<<(NNODES * 32 + 255) / 256, 256>>>(rowstart, ecol, eval_, w0, it1);
    ret_gather<<<(NNODES * 32 + 255) / 256, 256>>>(rowstart, ecol, eval_, it1, it2);

    // sage_out = LN(silu(proj + agg @ aggW))
    gemm_tc<1, 2><<<gemmGrid, 256, GEMM_SMEM>>>(agg, nullptr, bt + 2 * DDIM * DDIM,
                                                nullptr, proj, sage_ln_g, sage_ln_b, sage);
    // att_out = LN(v * weights)
    att_ln_kernel<<<1480, 256>>>(v, w0, it1, it2, att_ln_g, att_ln_b, att);

    // h = LN(silu(concat(sage,att) @ lin1_W + lin1_b))
    gemm_tc<2, 2><<<gemmGrid, 256, GEMM_SMEM>>>(sage, att, bt + 3 * DDIM * DDIM,
                                                lin1_b, nullptr, ln1_g, ln1_b, h);
    // out = LN(silu(h @ lin2_W + lin2_b + x))
    gemm_tc<1, 2><<<gemmGrid, 256, GEMM_SMEM>>>(h, nullptr, bt + 5 * DDIM * DDIM,
                                                lin2_b, x, ln2_g, ln2_b, out);
}

// round 8
// speedup vs baseline: 1.5867x; 1.5867x over previous
#include <cuda_runtime.h>
#include <math.h>

#define NNODES 50000
#define LDIM   4
#define DDIM   128
#define KDIM   16
#define EEDGES 800000
#define MROWS  (LDIM * NNODES)        // 200000, multiple of 64
#define DECAYF 0.7f
#define EPSF   1e-5f

// ---------------- scratch (device globals; no allocation) ----------------
__device__ float g_proj[MROWS * DDIM];
__device__ float g_v   [MROWS * DDIM];
__device__ float g_agg [MROWS * DDIM];
__device__ float g_sage[MROWS * DDIM];
__device__ float g_att [MROWS * DDIM];
__device__ float g_h   [MROWS * DDIM];
__device__ float g_w0 [MROWS];
__device__ float g_it1[MROWS];
__device__ float g_it2[MROWS];
__device__ float g_bt [6 * DDIM * DDIM];   // transposed weights [n][k]

// CSR build scratch
__device__ int   g_cnt[NNODES];
__device__ int   g_cur[NNODES];
__device__ int   g_rowstart[NNODES + 1];
__device__ int   g_ecol[EEDGES];
__device__ float g_eval[EEDGES];

// ================= weight transpose (once per launch, tiny) =================
struct SixPtr { const float* p[6]; };

// dst[m][n][k] = src_m[k*128 + n]
__global__ void transpose_kernel(SixPtr srcs, float* __restrict__ dst)
{
    __shared__ float tile[32][33];
    const int m = blockIdx.z;
    const float* src = srcs.p[m];
    float* d = dst + m * DDIM * DDIM;
    const int bx = blockIdx.x * 32;   // n tile
    const int by = blockIdx.y * 32;   // k tile
    const int tx = threadIdx.x, ty = threadIdx.y;
#pragma unroll
    for (int j = 0; j < 32; j += 8)
        tile[ty + j][tx] = src[(by + ty + j) * DDIM + bx + tx];
    __syncthreads();
#pragma unroll
    for (int j = 0; j < 32; j += 8)
        d[(bx + ty + j) * DDIM + by + tx] = tile[tx][ty + j];
}

// ================= CSR construction =================
__global__ void hist_kernel(const int* __restrict__ ei, int* __restrict__ cnt)
{
    int e = blockIdx.x * blockDim.x + threadIdx.x;
    if (e < EEDGES) atomicAdd(&cnt[ei[e]], 1);
}

__global__ void scan_kernel(const int* __restrict__ cnt, int* __restrict__ rowstart)
{
    const int T = 1024;
    __shared__ int partial[T];
    const int tid = threadIdx.x;
    const int chunk = (NNODES + T - 1) / T;
    const int base = tid * chunk;
    int s = 0;
    for (int i = 0; i < chunk; i++) {
        int idx = base + i;
        if (idx < NNODES) s += cnt[idx];
    }
    partial[tid] = s;
    __syncthreads();
    for (int off = 1; off < T; off <<= 1) {
        int v = (tid >= off) ? partial[tid - off] : 0;
        __syncthreads();
        partial[tid] += v;
        __syncthreads();
    }
    int run = (tid == 0) ? 0 : partial[tid - 1];
    for (int i = 0; i < chunk; i++) {
        int idx = base + i;
        if (idx < NNODES) { rowstart[idx] = run; run += cnt[idx]; }
    }
    if (tid == T - 1) rowstart[NNODES] = run;
}

__global__ void scatter_kernel(const int* __restrict__ ei, const float* __restrict__ ev,
                               const int* __restrict__ rowstart, int* __restrict__ cur,
                               int* __restrict__ ecol, float* __restrict__ eval_)
{
    int e = blockIdx.x * blockDim.x + threadIdx.x;
    if (e >= EEDGES) return;
    const int r = ei[e];
    const int pos = rowstart[r] + atomicAdd(&cur[r], 1);
    ecol[pos]  = ei[EEDGES + e];
    eval_[pos] = ev[e];
}

// ================= gather spmm (no atomics): warp per (row, l) =================
__global__ void __launch_bounds__(256) spmm_gather(
    const int* __restrict__ rowstart,
    const int* __restrict__ ecol, const float* __restrict__ eval_,
    const float* __restrict__ x, float* __restrict__ agg)
{
    const int gw = (blockIdx.x * blockDim.x + threadIdx.x) >> 5;
    const int lane = threadIdx.x & 31;
    const int row = gw >> 2;
    const int l   = gw & 3;
    if (row >= NNODES) return;

    const int s = rowstart[row];
    const int e = rowstart[row + 1];
    const float4* xl = (const float4*)x + (size_t)l * NNODES * 32;

    float4 acc = make_float4(0.f, 0.f, 0.f, 0.f);
    int i = s;
    for (; i + 2 <= e; i += 2) {
        const int   c0 = ecol[i],     c1 = ecol[i + 1];
        const float v0 = eval_[i],    v1 = eval_[i + 1];
        float4 x0 = xl[(size_t)c0 * 32 + lane];
        float4 x1 = xl[(size_t)c1 * 32 + lane];
        acc.x += v0 * x0.x; acc.y += v0 * x0.y; acc.z += v0 * x0.z; acc.w += v0 * x0.w;
        acc.x += v1 * x1.x; acc.y += v1 * x1.y; acc.z += v1 * x1.z; acc.w += v1 * x1.w;
    }
    if (i < e) {
        const int c0 = ecol[i];
        const float v0 = eval_[i];
        float4 x0 = xl[(size_t)c0 * 32 + lane];
        acc.x += v0 * x0.x; acc.y += v0 * x0.y; acc.z += v0 * x0.z; acc.w += v0 * x0.w;
    }
    ((float4*)agg)[((size_t)l * NNODES + row) * 32 + lane] = acc;
}

// ================= retention spmm on [L,N] weights (gather) =================
__global__ void __launch_bounds__(256) ret_gather(
    const int* __restrict__ rowstart,
    const int* __restrict__ ecol, const float* __restrict__ eval_,
    const float* __restrict__ src, float* __restrict__ dst)
{
    const int row = (blockIdx.x * blockDim.x + threadIdx.x) >> 5;
    const int lane = threadIdx.x & 31;
    if (row >= NNODES) return;
    const int s = rowstart[row];
    const int e = rowstart[row + 1];

    float a0 = 0.f, a1 = 0.f, a2 = 0.f, a3 = 0.f;
    for (int i = s + lane; i < e; i += 32) {
        const int c = ecol[i];
        const float v = DECAYF * eval_[i];
        a0 += v * src[c];
        a1 += v * src[NNODES + c];
        a2 += v * src[2 * NNODES + c];
        a3 += v * src[3 * NNODES + c];
    }
#pragma unroll
    for (int off = 16; off; off >>= 1) {
        a0 += __shfl_xor_sync(0xFFFFFFFFu, a0, off);
        a1 += __shfl_xor_sync(0xFFFFFFFFu, a1, off);
        a2 += __shfl_xor_sync(0xFFFFFFFFu, a2, off);
        a3 += __shfl_xor_sync(0xFFFFFFFFu, a3, off);
    }
    if (lane == 0) {
        dst[row]              = a0;
        dst[NNODES + row]     = a1;
        dst[2 * NNODES + row] = a2;
        dst[3 * NNODES + row] = a3;
    }
}

// ================= tf32 tensor-core GEMM (R3 shape + ldmatrix) ==============
// C[M,128] = A[M, NCHUNK*128] @ B (B pre-transposed: Bt[n][k]).
// Block: 64 rows x 128 cols, 8 warps, 2 CTAs/SM.
// Warp (wr,wc): rows wr*16..+15, cols wc*64..+63.
#define AST 132
#define BST 132
#define GEMM_SMEM ((64 * AST + 128 * BST) * 4)   // 101376 bytes

__device__ __forceinline__ unsigned f2tf(float f)
{
    unsigned u;
    asm("cvt.rna.tf32.f32 %0, %1;" : "=r"(u) : "f"(f));
    return u;
}

__device__ __forceinline__ void mma8(float* c, const unsigned* a, unsigned b0, unsigned b1)
{
    asm volatile(
        "mma.sync.aligned.m16n8k8.row.col.f32.tf32.tf32.f32 "
        "{%0,%1,%2,%3},{%4,%5,%6,%7},{%8,%9},{%0,%1,%2,%3};"
        : "+f"(c[0]), "+f"(c[1]), "+f"(c[2]), "+f"(c[3])
        : "r"(a[0]), "r"(a[1]), "r"(a[2]), "r"(a[3]), "r"(b0), "r"(b1));
}

#define LDSM4(r, addr) \
    asm volatile("ldmatrix.sync.aligned.m8n8.x4.shared.b16 {%0,%1,%2,%3}, [%4];" \
        : "=r"((r)[0]), "=r"((r)[1]), "=r"((r)[2]), "=r"((r)[3]) : "r"(addr))

template <int NCHUNK, int EPI>
__global__ void __launch_bounds__(256, 2) gemm_tc(
    const float* __restrict__ A0, const float* __restrict__ A1,
    const float* __restrict__ Bt,
    const float* __restrict__ bias, const float* __restrict__ addb,
    const float* __restrict__ lng, const float* __restrict__ lnb,
    float* __restrict__ C)
{
    extern __shared__ unsigned smem_u[];
    unsigned* As = smem_u;            // 64 x AST tf32
    unsigned* Bs = smem_u + 64 * AST; // 128 x BST tf32 ([n][k])
    float* Cs = (float*)smem_u;       // epilogue staging

    const int tid  = threadIdx.x;
    const int lane = tid & 31;
    const int wid  = tid >> 5;
    const int wr   = wid & 3;    // rows wr*16
    const int wc   = wid >> 2;   // cols wc*64
    const int tg   = lane & 3;
    const int gr   = lane >> 2;
    const int blockRow = blockIdx.x * 64;

    // ldmatrix per-thread addresses (bytes, shared space)
    const unsigned sbase = (unsigned)__cvta_generic_to_shared(smem_u);
    const unsigned aAddr = sbase +
        ((wr * 16 + (lane & 15)) * AST + (lane >> 4) * 4) * 4u;
    const unsigned bAddr = sbase + 64u * AST * 4u +
        ((wc * 64 + (lane >> 4) * 8 + (lane & 7)) * BST + ((lane >> 3) & 1) * 4) * 4u;

    float acc[8][4];
#pragma unroll
    for (int i = 0; i < 8; i++)
#pragma unroll
        for (int j = 0; j < 4; j++) acc[i][j] = 0.f;

#pragma unroll
    for (int ch = 0; ch < NCHUNK; ch++) {
        const float* A = (NCHUNK == 2 && ch == 1) ? A1 : A0;
        // A tile: 64 consecutive rows = 8192 contiguous floats
        const float4* Ag = (const float4*)(A + (size_t)blockRow * DDIM);
#pragma unroll
        for (int f = 0; f < 8; f++) {
            int i4 = tid + f * 256;
            float4 v = Ag[i4];
            int e = i4 * 4;
            uint4 t = make_uint4(f2tf(v.x), f2tf(v.y), f2tf(v.z), f2tf(v.w));
            *(uint4*)(As + (e >> 7) * AST + (e & 127)) = t;
        }
        // B tile: Bt chunk [128][128] contiguous -> Bs[n][k] padded
        const float4* Bg = (const float4*)(Bt + ch * DDIM * DDIM);
#pragma unroll
        for (int f = 0; f < 16; f++) {
            int i4 = tid + f * 256;
            float4 v = Bg[i4];
            int e = i4 * 4;
            uint4 t = make_uint4(f2tf(v.x), f2tf(v.y), f2tf(v.z), f2tf(v.w));
            *(uint4*)(Bs + (e >> 7) * BST + (e & 127)) = t;
        }
        __syncthreads();

#pragma unroll
        for (int k8 = 0; k8 < 16; k8++) {
            const unsigned ko = k8 * 32;   // 8 tf32 = 32 bytes
            unsigned af[4], bf[4][4];
            LDSM4(af, aAddr + ko);
            LDSM4(bf[0], bAddr + ko);
            LDSM4(bf[1], bAddr + 16 * BST * 4 + ko);
            LDSM4(bf[2], bAddr + 32 * BST * 4 + ko);
            LDSM4(bf[3], bAddr + 48 * BST * 4 + ko);
#pragma unroll
            for (int nt = 0; nt < 8; nt++) {
                const unsigned b0 = bf[nt >> 1][(nt & 1) * 2];
                const unsigned b1 = bf[nt >> 1][(nt & 1) * 2 + 1];
                mma8(acc[nt], af, b0, b1);
            }
        }
        __syncthreads();
    }

    // stage acc into smem (row-major 64 x AST floats)
    {
        const int r0 = wr * 16 + gr;
#pragma unroll
        for (int nt = 0; nt < 8; nt++) {
            const int c = wc * 64 + nt * 8 + 2 * tg;
            *(float2*)(Cs + r0 * AST + c)       = make_float2(acc[nt][0], acc[nt][1]);
            *(float2*)(Cs + (r0 + 8) * AST + c) = make_float2(acc[nt][2], acc[nt][3]);
        }
    }
    __syncthreads();

    // epilogue: warp wid owns rows wid*8..+7; lane owns 4 cols
    float4 bias4 = make_float4(0.f, 0.f, 0.f, 0.f);
    if (EPI >= 1 && bias) bias4 = ((const float4*)bias)[lane];

    if constexpr (EPI == 2) {
        const float4 g4 = ((const float4*)lng)[lane];
        const float4 b4 = ((const float4*)lnb)[lane];
#pragma unroll
        for (int i = 0; i < 8; i++) {
            const int r = wid * 8 + i;
            const size_t gr_ = (size_t)blockRow + r;
            float4 t = *(const float4*)(Cs + r * AST + lane * 4);
            t.x += bias4.x; t.y += bias4.y; t.z += bias4.z; t.w += bias4.w;
            if (addb) {
                float4 ad = ((const float4*)addb)[gr_ * 32 + lane];
                t.x += ad.x; t.y += ad.y; t.z += ad.z; t.w += ad.w;
            }
            float4 s;
            s.x = t.x / (1.f + expf(-t.x));
            s.y = t.y / (1.f + expf(-t.y));
            s.z = t.z / (1.f + expf(-t.z));
            s.w = t.w / (1.f + expf(-t.w));
            float sum = s.x + s.y + s.z + s.w;
            float sq  = s.x * s.x + s.y * s.y + s.z * s.z + s.w * s.w;
#pragma unroll
            for (int off = 16; off; off >>= 1) {
                sum += __shfl_xor_sync(0xFFFFFFFFu, sum, off);
                sq  += __shfl_xor_sync(0xFFFFFFFFu, sq,  off);
            }
            const float mean = sum * (1.f / 128.f);
            const float var  = sq * (1.f / 128.f) - mean * mean;
            const float rstd = rsqrtf(var + EPSF);
            float4 o;
            o.x = (s.x - mean) * rstd * g4.x + b4.x;
            o.y = (s.y - mean) * rstd * g4.y + b4.y;
            o.z = (s.z - mean) * rstd * g4.z + b4.z;
            o.w = (s.w - mean) * rstd * g4.w + b4.w;
            ((float4*)C)[gr_ * 32 + lane] = o;
        }
    } else {
#pragma unroll
        for (int i = 0; i < 8; i++) {
            const int r = wid * 8 + i;
            const size_t gr_ = (size_t)blockRow + r;
            float4 t = *(const float4*)(Cs + r * AST + lane * 4);
            t.x += bias4.x; t.y += bias4.y; t.z += bias4.z; t.w += bias4.w;
            ((float4*)C)[gr_ * 32 + lane] = t;
        }
    }
}

// ---------------- k/q retention weights ----------------
__global__ void kq_kernel(const float* __restrict__ x,
                          const float* __restrict__ Wk, const float* __restrict__ Wq,
                          float* __restrict__ w0)
{
    __shared__ float4 sk4[KDIM * 32];
    __shared__ float4 sq4[KDIM * 32];
    float* sk = (float*)sk4;
    float* sqm = (float*)sq4;
    for (int idx = threadIdx.x; idx < DDIM * KDIM; idx += blockDim.x) {
        int k = idx >> 4, j = idx & 15;
        sk[j * DDIM + k] = Wk[idx];
        sqm[j * DDIM + k] = Wq[idx];
    }
    __syncthreads();

    const int lane = threadIdx.x & 31;
    int warp = (blockIdx.x * blockDim.x + threadIdx.x) >> 5;
    const int nwarps = (gridDim.x * blockDim.x) >> 5;

    for (size_t r = warp; r < (size_t)MROWS; r += nwarps) {
        const float4 xv = ((const float4*)x)[r * 32 + lane];
        float pk[KDIM], pq[KDIM];
#pragma unroll
        for (int j = 0; j < KDIM; j++) {
            float4 wk = sk4[j * 32 + lane];
            float4 wq = sq4[j * 32 + lane];
            pk[j] = xv.x * wk.x + xv.y * wk.y + xv.z * wk.z + xv.w * wk.w;
            pq[j] = xv.x * wq.x + xv.y * wq.y + xv.z * wq.z + xv.w * wq.w;
        }
#pragma unroll
        for (int off = 16; off; off >>= 1) {
#pragma unroll
            for (int j = 0; j < KDIM; j++) {
                pk[j] += __shfl_xor_sync(0xFFFFFFFFu, pk[j], off);
                pq[j] += __shfl_xor_sync(0xFFFFFFFFu, pq[j], off);
            }
        }
        if (lane == 0) {
            float s = 0.f;
#pragma unroll
            for (int j = 0; j < KDIM; j++) s += pk[j] * pq[j];
            w0[r] = s * (1.f / (float)KDIM);
        }
    }
}

// ---------------- attention output: att = LN(v * (w0+it1+it2)) ----------------
__global__ void att_ln_kernel(const float* __restrict__ v,
                              const float* __restrict__ w0, const float* __restrict__ it1,
                              const float* __restrict__ it2,
                              const float* __restrict__ g, const float* __restrict__ b,
                              float* __restrict__ out)
{
    const int lane = threadIdx.x & 31;
    int warp = (blockIdx.x * blockDim.x + threadIdx.x) >> 5;
    const int nwarps = (gridDim.x * blockDim.x) >> 5;
    const float4 g4 = ((const float4*)g)[lane];
    const float4 b4 = ((const float4*)b)[lane];

    for (size_t r = warp; r < (size_t)MROWS; r += nwarps) {
        const float w = w0[r] + it1[r] + it2[r];
        float4 s = ((const float4*)v)[r * 32 + lane];
        s.x *= w; s.y *= w; s.z *= w; s.w *= w;
        float sum = s.x + s.y + s.z + s.w;
        float sq  = s.x * s.x + s.y * s.y + s.z * s.z + s.w * s.w;
#pragma unroll
        for (int off = 16; off; off >>= 1) {
            sum += __shfl_xor_sync(0xFFFFFFFFu, sum, off);
            sq  += __shfl_xor_sync(0xFFFFFFFFu, sq,  off);
        }
        const float mean = sum * (1.f / 128.f);
        const float var  = sq * (1.f / 128.f) - mean * mean;
        const float rstd = rsqrtf(var + EPSF);
        float4 o;
        o.x = (s.x - mean) * rstd * g4.x + b4.x;
        o.y = (s.y - mean) * rstd * g4.y + b4.y;
        o.z = (s.z - mean) * rstd * g4.z + b4.z;
        o.w = (s.w - mean) * rstd * g4.w + b4.w;
        ((float4*)out)[r * 32 + lane] = o;
    }
}

// ---------------- host ----------------
extern "C" void kernel_launch(void* const* d_in, const int* in_sizes, int n_in,
                              void* d_out, int out_size)
{
    const float* x          = (const float*)d_in[0];
    const int*   ei         = (const int*)  d_in[1];
    const float* ev         = (const float*)d_in[2];
    const float* sage_W     = (const float*)d_in[3];
    const float* sage_b     = (const float*)d_in[4];
    const float* sage_aggW  = (const float*)d_in[5];
    const float* sage_ln_g  = (const float*)d_in[6];
    const float* sage_ln_b  = (const float*)d_in[7];
    const float* att_Wk     = (const float*)d_in[8];
    const float* att_Wq     = (const float*)d_in[9];
    const float* att_Wv     = (const float*)d_in[10];
    const float* att_ln_g   = (const float*)d_in[11];
    const float* att_ln_b   = (const float*)d_in[12];
    const float* lin1_W     = (const float*)d_in[13];
    const float* lin1_b     = (const float*)d_in[14];
    const float* lin2_W     = (const float*)d_in[15];
    const float* lin2_b     = (const float*)d_in[16];
    const float* ln1_g      = (const float*)d_in[17];
    const float* ln1_b      = (const float*)d_in[18];
    const float* ln2_g      = (const float*)d_in[19];
    const float* ln2_b      = (const float*)d_in[20];
    float* out = (float*)d_out;

    float *proj, *v, *agg, *sage, *att, *h, *w0, *it1, *it2, *bt;
    cudaGetSymbolAddress((void**)&proj, g_proj);
    cudaGetSymbolAddress((void**)&v,    g_v);
    cudaGetSymbolAddress((void**)&agg,  g_agg);
    cudaGetSymbolAddress((void**)&sage, g_sage);
    cudaGetSymbolAddress((void**)&att,  g_att);
    cudaGetSymbolAddress((void**)&h,    g_h);
    cudaGetSymbolAddress((void**)&w0,   g_w0);
    cudaGetSymbolAddress((void**)&it1,  g_it1);
    cudaGetSymbolAddress((void**)&it2,  g_it2);
    cudaGetSymbolAddress((void**)&bt,   g_bt);

    int *cnt, *cur, *rowstart, *ecol;
    float *eval_;
    cudaGetSymbolAddress((void**)&cnt,      g_cnt);
    cudaGetSymbolAddress((void**)&cur,      g_cur);
    cudaGetSymbolAddress((void**)&rowstart, g_rowstart);
    cudaGetSymbolAddress((void**)&ecol,     g_ecol);
    cudaGetSymbolAddress((void**)&eval_,    g_eval);

    cudaFuncSetAttribute(gemm_tc<1, 0>, cudaFuncAttributeMaxDynamicSharedMemorySize, GEMM_SMEM);
    cudaFuncSetAttribute(gemm_tc<1, 1>, cudaFuncAttributeMaxDynamicSharedMemorySize, GEMM_SMEM);
    cudaFuncSetAttribute(gemm_tc<1, 2>, cudaFuncAttributeMaxDynamicSharedMemorySize, GEMM_SMEM);
    cudaFuncSetAttribute(gemm_tc<2, 2>, cudaFuncAttributeMaxDynamicSharedMemorySize, GEMM_SMEM);

    const int gemmGrid = MROWS / 64; // 3125

    // ---- weight transposes: [0]=sage_W [1]=att_Wv [2]=sage_aggW [3,4]=lin1 [5]=lin2 ----
    SixPtr sp;
    sp.p[0] = sage_W; sp.p[1] = att_Wv; sp.p[2] = sage_aggW;
    sp.p[3] = lin1_W; sp.p[4] = lin1_W + DDIM * DDIM; sp.p[5] = lin2_W;
    {
        dim3 tg(4, 4, 6), tb(32, 8);
        transpose_kernel<<<tg, tb>>>(sp, bt);
    }

    // ---- CSR build ----
    cudaMemsetAsync(cnt, 0, NNODES * sizeof(int), 0);
    cudaMemsetAsync(cur, 0, NNODES * sizeof(int), 0);
    hist_kernel<<<(EEDGES + 255) / 256, 256>>>(ei, cnt);
    scan_kernel<<<1, 1024>>>(cnt, rowstart);
    scatter_kernel<<<(EEDGES + 255) / 256, 256>>>(ei, ev, rowstart, cur, ecol, eval_);

    // proj = x @ sage_W + sage_b ; v = x @ att_Wv
    gemm_tc<1, 1><<<gemmGrid, 256, GEMM_SMEM>>>(x, nullptr, bt + 0 * DDIM * DDIM,
                                                sage_b, nullptr, nullptr, nullptr, proj);
    gemm_tc<1, 0><<<gemmGrid, 256, GEMM_SMEM>>>(x, nullptr, bt + 1 * DDIM * DDIM,
                                                nullptr, nullptr, nullptr, nullptr, v);

    // retention base weights
    kq_kernel<<<1480, 256>>>(x, att_Wk, att_Wq, w0);

    // graph aggregation: gather, warp per (row, l)
    spmm_gather<<<(NNODES * 4 * 32 + 255) / 256, 256>>>(rowstart, ecol, eval_, x, agg);

    // retention iterations
    ret_gather<<<(NNODES * 32 + 255) / 256, 256>>>(rowstart, ecol, eval_, w0, it1);
    ret_gather<<<(NNODES * 32 + 255) / 256, 256>>>(rowstart, ecol, eval_, it1, it2);

    // sage_out = LN(silu(proj + agg @ aggW))
    gemm_tc<1, 2><<<gemmGrid, 256, GEMM_SMEM>>>(agg, nullptr, bt + 2 * DDIM * DDIM,
                                                nullptr, proj, sage_ln_g, sage_ln_b, sage);
    // att_out = LN(v * weights)
    att_ln_kernel<<<1480, 256>>>(v, w0, it1, it2, att_ln_g, att_ln_b, att);

    // h = LN(silu(concat(sage,att) @ lin1_W + lin1_b))
    gemm_tc<2, 2><<<gemmGrid, 256, GEMM_SMEM>>>(sage, att, bt + 3 * DDIM * DDIM,
                                                lin1_b, nullptr, ln1_g, ln1_b, h);
    // out = LN(silu(h @ lin2_W + lin2_b + x))
    gemm_tc<1, 2><<<gemmGrid, 256, GEMM_SMEM>>>(h, nullptr, bt + 5 * DDIM * DDIM,
                                                lin2_b, x, ln2_g, ln2_b, out);
}

// round 10
// speedup vs baseline: 1.6037x; 1.0107x over previous
#include <cuda_runtime.h>
#include <math.h>

#define NNODES 50000
#define LDIM   4
#define DDIM   128
#define KDIM   16
#define EEDGES 800000
#define MROWS  (LDIM * NNODES)        // 200000, multiple of 64
#define DECAYF 0.7f
#define EPSF   1e-5f

// ---------------- scratch (device globals; no allocation) ----------------
__device__ float g_proj[MROWS * DDIM];
__device__ float g_v   [MROWS * DDIM];
__device__ float g_agg [MROWS * DDIM];
__device__ float g_sage[MROWS * DDIM];
__device__ float g_att [MROWS * DDIM];
__device__ float g_h   [MROWS * DDIM];
__device__ float g_w0 [MROWS];
__device__ float g_it1[MROWS];
__device__ float g_it2[MROWS];
__device__ float g_bt [6 * DDIM * DDIM];   // transposed weights [n][k]

// CSR build scratch
__device__ int   g_cnt[NNODES];
__device__ int   g_cur[NNODES];
__device__ int   g_rowstart[NNODES + 1];
__device__ int   g_ecol[EEDGES];
__device__ float g_eval[EEDGES];

// ================= weight transpose (once per launch, tiny) =================
struct SixPtr { const float* p[6]; };

__global__ void transpose_kernel(SixPtr srcs, float* __restrict__ dst)
{
    __shared__ float tile[32][33];
    const int m = blockIdx.z;
    const float* src = srcs.p[m];
    float* d = dst + m * DDIM * DDIM;
    const int bx = blockIdx.x * 32;
    const int by = blockIdx.y * 32;
    const int tx = threadIdx.x, ty = threadIdx.y;
#pragma unroll
    for (int j = 0; j < 32; j += 8)
        tile[ty + j][tx] = src[(by + ty + j) * DDIM + bx + tx];
    __syncthreads();
#pragma unroll
    for (int j = 0; j < 32; j += 8)
        d[(bx + ty + j) * DDIM + by + tx] = tile[tx][ty + j];
}

// ================= CSR construction =================
__global__ void hist_kernel(const int* __restrict__ ei, int* __restrict__ cnt)
{
    int e = blockIdx.x * blockDim.x + threadIdx.x;
    if (e < EEDGES) atomicAdd(&cnt[ei[e]], 1);
}

__global__ void scan_kernel(const int* __restrict__ cnt, int* __restrict__ rowstart)
{
    const int T = 1024;
    __shared__ int partial[T];
    const int tid = threadIdx.x;
    const int chunk = (NNODES + T - 1) / T;
    const int base = tid * chunk;
    int s = 0;
    for (int i = 0; i < chunk; i++) {
        int idx = base + i;
        if (idx < NNODES) s += cnt[idx];
    }
    partial[tid] = s;
    __syncthreads();
    for (int off = 1; off < T; off <<= 1) {
        int v = (tid >= off) ? partial[tid - off] : 0;
        __syncthreads();
        partial[tid] += v;
        __syncthreads();
    }
    int run = (tid == 0) ? 0 : partial[tid - 1];
    for (int i = 0; i < chunk; i++) {
        int idx = base + i;
        if (idx < NNODES) { rowstart[idx] = run; run += cnt[idx]; }
    }
    if (tid == T - 1) rowstart[NNODES] = run;
}

__global__ void scatter_kernel(const int* __restrict__ ei, const float* __restrict__ ev,
                               const int* __restrict__ rowstart, int* __restrict__ cur,
                               int* __restrict__ ecol, float* __restrict__ eval_)
{
    int e = blockIdx.x * blockDim.x + threadIdx.x;
    if (e >= EEDGES) return;
    const int r = ei[e];
    const int pos = rowstart[r] + atomicAdd(&cur[r], 1);
    ecol[pos]  = ei[EEDGES + e];
    eval_[pos] = ev[e];
}

// ================= gather spmm (no atomics): warp per (row, l), unroll 4 =====
__global__ void __launch_bounds__(256) spmm_gather(
    const int* __restrict__ rowstart,
    const int* __restrict__ ecol, const float* __restrict__ eval_,
    const float* __restrict__ x, float* __restrict__ agg)
{
    const int gw = (blockIdx.x * blockDim.x + threadIdx.x) >> 5;
    const int lane = threadIdx.x & 31;
    const int row = gw >> 2;
    const int l   = gw & 3;
    if (row >= NNODES) return;

    const int s = rowstart[row];
    const int e = rowstart[row + 1];
    const float4* xl = (const float4*)x + (size_t)l * NNODES * 32;

    float4 acc = make_float4(0.f, 0.f, 0.f, 0.f);
    int i = s;
    for (; i + 4 <= e; i += 4) {
        const int   c0 = ecol[i],   c1 = ecol[i+1], c2 = ecol[i+2], c3 = ecol[i+3];
        const float v0 = eval_[i],  v1 = eval_[i+1], v2 = eval_[i+2], v3 = eval_[i+3];
        float4 x0 = xl[(size_t)c0 * 32 + lane];
        float4 x1 = xl[(size_t)c1 * 32 + lane];
        float4 x2 = xl[(size_t)c2 * 32 + lane];
        float4 x3 = xl[(size_t)c3 * 32 + lane];
        acc.x += v0 * x0.x; acc.y += v0 * x0.y; acc.z += v0 * x0.z; acc.w += v0 * x0.w;
        acc.x += v1 * x1.x; acc.y += v1 * x1.y; acc.z += v1 * x1.z; acc.w += v1 * x1.w;
        acc.x += v2 * x2.x; acc.y += v2 * x2.y; acc.z += v2 * x2.z; acc.w += v2 * x2.w;
        acc.x += v3 * x3.x; acc.y += v3 * x3.y; acc.z += v3 * x3.z; acc.w += v3 * x3.w;
    }
    for (; i < e; i++) {
        const int c0 = ecol[i];
        const float v0 = eval_[i];
        float4 x0 = xl[(size_t)c0 * 32 + lane];
        acc.x += v0 * x0.x; acc.y += v0 * x0.y; acc.z += v0 * x0.z; acc.w += v0 * x0.w;
    }
    ((float4*)agg)[((size_t)l * NNODES + row) * 32 + lane] = acc;
}

// ================= retention spmm on [L,N] weights (gather) =================
__global__ void __launch_bounds__(256) ret_gather(
    const int* __restrict__ rowstart,
    const int* __restrict__ ecol, const float* __restrict__ eval_,
    const float* __restrict__ src, float* __restrict__ dst)
{
    const int row = (blockIdx.x * blockDim.x + threadIdx.x) >> 5;
    const int lane = threadIdx.x & 31;
    if (row >= NNODES) return;
    const int s = rowstart[row];
    const int e = rowstart[row + 1];

    float a0 = 0.f, a1 = 0.f, a2 = 0.f, a3 = 0.f;
    for (int i = s + lane; i < e; i += 32) {
        const int c = ecol[i];
        const float v = DECAYF * eval_[i];
        a0 += v * src[c];
        a1 += v * src[NNODES + c];
        a2 += v * src[2 * NNODES + c];
        a3 += v * src[3 * NNODES + c];
    }
#pragma unroll
    for (int off = 16; off; off >>= 1) {
        a0 += __shfl_xor_sync(0xFFFFFFFFu, a0, off);
        a1 += __shfl_xor_sync(0xFFFFFFFFu, a1, off);
        a2 += __shfl_xor_sync(0xFFFFFFFFu, a2, off);
        a3 += __shfl_xor_sync(0xFFFFFFFFu, a3, off);
    }
    if (lane == 0) {
        dst[row]              = a0;
        dst[NNODES + row]     = a1;
        dst[2 * NNODES + row] = a2;
        dst[3 * NNODES + row] = a3;
    }
}

// ================= common MMA helpers =================
#define AST 132
#define BST 132
#define GEMM_SMEM ((64 * AST + 128 * BST) * 4)   // 101376 bytes

__device__ __forceinline__ unsigned f2tf(float f)
{
    unsigned u;
    asm("cvt.rna.tf32.f32 %0, %1;" : "=r"(u) : "f"(f));
    return u;
}

__device__ __forceinline__ void mma8(float* c, const unsigned* a, unsigned b0, unsigned b1)
{
    asm volatile(
        "mma.sync.aligned.m16n8k8.row.col.f32.tf32.tf32.f32 "
        "{%0,%1,%2,%3},{%4,%5,%6,%7},{%8,%9},{%0,%1,%2,%3};"
        : "+f"(c[0]), "+f"(c[1]), "+f"(c[2]), "+f"(c[3])
        : "r"(a[0]), "r"(a[1]), "r"(a[2]), "r"(a[3]), "r"(b0), "r"(b1));
}

#define LDSM4(r, addr) \
    asm volatile("ldmatrix.sync.aligned.m8n8.x4.shared.b16 {%0,%1,%2,%3}, [%4];" \
        : "=r"((r)[0]), "=r"((r)[1]), "=r"((r)[2]), "=r"((r)[3]) : "r"(addr))

// ================= fused pre_kernel: proj + v from ONE read of x =============
__global__ void __launch_bounds__(256, 2) pre_kernel(
    const float* __restrict__ x, const float* __restrict__ bt_pv,
    const float* __restrict__ sage_b,
    float* __restrict__ proj, float* __restrict__ v)
{
    extern __shared__ unsigned smem_u[];
    unsigned* As = smem_u;            // 64 x AST
    unsigned* Bs = smem_u + 64 * AST; // 128 x BST ([n][k])

    const int tid  = threadIdx.x;
    const int lane = tid & 31;
    const int wid  = tid >> 5;
    const int wr   = wid & 3;
    const int wc   = wid >> 2;
    const int tg   = lane & 3;
    const int gr   = lane >> 2;
    const int blockRow = blockIdx.x * 64;

    const unsigned sbase = (unsigned)__cvta_generic_to_shared(smem_u);
    const unsigned aAddr = sbase +
        ((wr * 16 + (lane & 15)) * AST + (lane >> 4) * 4) * 4u;
    const unsigned bAddr = sbase + 64u * AST * 4u +
        ((wc * 64 + (lane >> 4) * 8 + (lane & 7)) * BST + ((lane >> 3) & 1) * 4) * 4u;

    // A tile fill (once)
    {
        const float4* Ag = (const float4*)(x + (size_t)blockRow * DDIM);
#pragma unroll
        for (int f = 0; f < 8; f++) {
            int i4 = tid + f * 256;
            float4 t = Ag[i4];
            int e = i4 * 4;
            *(uint4*)(As + (e >> 7) * AST + (e & 127)) =
                make_uint4(f2tf(t.x), f2tf(t.y), f2tf(t.z), f2tf(t.w));
        }
    }

    float acc[8][4];

#pragma unroll
    for (int pass = 0; pass < 2; pass++) {
        const float4* Bg = (const float4*)(bt_pv + pass * DDIM * DDIM);
#pragma unroll
        for (int f = 0; f < 16; f++) {
            int i4 = tid + f * 256;
            float4 t = Bg[i4];
            int e = i4 * 4;
            *(uint4*)(Bs + (e >> 7) * BST + (e & 127)) =
                make_uint4(f2tf(t.x), f2tf(t.y), f2tf(t.z), f2tf(t.w));
        }
        __syncthreads();

#pragma unroll
        for (int i = 0; i < 8; i++)
#pragma unroll
            for (int j = 0; j < 4; j++) acc[i][j] = 0.f;

#pragma unroll
        for (int k8 = 0; k8 < 16; k8++) {
            const unsigned ko = k8 * 32;
            unsigned af[4], bf[4][4];
            LDSM4(af, aAddr + ko);
            LDSM4(bf[0], bAddr + ko);
            LDSM4(bf[1], bAddr + 16 * BST * 4 + ko);
            LDSM4(bf[2], bAddr + 32 * BST * 4 + ko);
            LDSM4(bf[3], bAddr + 48 * BST * 4 + ko);
#pragma unroll
            for (int nt = 0; nt < 8; nt++)
                mma8(acc[nt], af, bf[nt >> 1][(nt & 1) * 2], bf[nt >> 1][(nt & 1) * 2 + 1]);
        }
        __syncthreads();   // protect Bs before next pass refill

        // direct fragment store (+ sage_b on pass 0)
        float* C = pass ? v : proj;
        const int r0 = blockRow + wr * 16 + gr;
#pragma unroll
        for (int nt = 0; nt < 8; nt++) {
            const int c = wc * 64 + nt * 8 + 2 * tg;
            float2 b2 = make_float2(0.f, 0.f);
            if (pass == 0) b2 = ((const float2*)sage_b)[c >> 1];
            ((float2*)C)[(size_t)r0 * 64 + (c >> 1)] =
                make_float2(acc[nt][0] + b2.x, acc[nt][1] + b2.y);
            ((float2*)C)[(size_t)(r0 + 8) * 64 + (c >> 1)] =
                make_float2(acc[nt][2] + b2.x, acc[nt][3] + b2.y);
        }
    }
}

// ================= tf32 GEMM with fused LN epilogue (R5 proven) ==============
template <int NCHUNK, int EPI>
__global__ void __launch_bounds__(256, 2) gemm_tc(
    const float* __restrict__ A0, const float* __restrict__ A1,
    const float* __restrict__ Bt,
    const float* __restrict__ bias, const float* __restrict__ addb,
    const float* __restrict__ lng, const float* __restrict__ lnb,
    float* __restrict__ C)
{
    extern __shared__ unsigned smem_u[];
    unsigned* As = smem_u;
    unsigned* Bs = smem_u + 64 * AST;
    float* Cs = (float*)smem_u;

    const int tid  = threadIdx.x;
    const int lane = tid & 31;
    const int wid  = tid >> 5;
    const int wr   = wid & 3;
    const int wc   = wid >> 2;
    const int tg   = lane & 3;
    const int gr   = lane >> 2;
    const int blockRow = blockIdx.x * 64;

    const unsigned sbase = (unsigned)__cvta_generic_to_shared(smem_u);
    const unsigned aAddr = sbase +
        ((wr * 16 + (lane & 15)) * AST + (lane >> 4) * 4) * 4u;
    const unsigned bAddr = sbase + 64u * AST * 4u +
        ((wc * 64 + (lane >> 4) * 8 + (lane & 7)) * BST + ((lane >> 3) & 1) * 4) * 4u;

    float acc[8][4];
#pragma unroll
    for (int i = 0; i < 8; i++)
#pragma unroll
        for (int j = 0; j < 4; j++) acc[i][j] = 0.f;

#pragma unroll
    for (int ch = 0; ch < NCHUNK; ch++) {
        const float* A = (NCHUNK == 2 && ch == 1) ? A1 : A0;
        const float4* Ag = (const float4*)(A + (size_t)blockRow * DDIM);
#pragma unroll
        for (int f = 0; f < 8; f++) {
            int i4 = tid + f * 256;
            float4 t = Ag[i4];
            int e = i4 * 4;
            *(uint4*)(As + (e >> 7) * AST + (e & 127)) =
                make_uint4(f2tf(t.x), f2tf(t.y), f2tf(t.z), f2tf(t.w));
        }
        const float4* Bg = (const float4*)(Bt + ch * DDIM * DDIM);
#pragma unroll
        for (int f = 0; f < 16; f++) {
            int i4 = tid + f * 256;
            float4 t = Bg[i4];
            int e = i4 * 4;
            *(uint4*)(Bs + (e >> 7) * BST + (e & 127)) =
                make_uint4(f2tf(t.x), f2tf(t.y), f2tf(t.z), f2tf(t.w));
        }
        __syncthreads();

#pragma unroll
        for (int k8 = 0; k8 < 16; k8++) {
            const unsigned ko = k8 * 32;
            unsigned af[4], bf[4][4];
            LDSM4(af, aAddr + ko);
            LDSM4(bf[0], bAddr + ko);
            LDSM4(bf[1], bAddr + 16 * BST * 4 + ko);
            LDSM4(bf[2], bAddr + 32 * BST * 4 + ko);
            LDSM4(bf[3], bAddr + 48 * BST * 4 + ko);
#pragma unroll
            for (int nt = 0; nt < 8; nt++)
                mma8(acc[nt], af, bf[nt >> 1][(nt & 1) * 2], bf[nt >> 1][(nt & 1) * 2 + 1]);
        }
        __syncthreads();
    }

    {
        const int r0 = wr * 16 + gr;
#pragma unroll
        for (int nt = 0; nt < 8; nt++) {
            const int c = wc * 64 + nt * 8 + 2 * tg;
            *(float2*)(Cs + r0 * AST + c)       = make_float2(acc[nt][0], acc[nt][1]);
            *(float2*)(Cs + (r0 + 8) * AST + c) = make_float2(acc[nt][2], acc[nt][3]);
        }
    }
    __syncthreads();

    float4 bias4 = make_float4(0.f, 0.f, 0.f, 0.f);
    if (EPI >= 1 && bias) bias4 = ((const float4*)bias)[lane];

    if constexpr (EPI == 2) {
        const float4 g4 = ((const float4*)lng)[lane];
        const float4 b4 = ((const float4*)lnb)[lane];
#pragma unroll
        for (int i = 0; i < 8; i++) {
            const int r = wid * 8 + i;
            const size_t gr_ = (size_t)blockRow + r;
            float4 t = *(const float4*)(Cs + r * AST + lane * 4);
            t.x += bias4.x; t.y += bias4.y; t.z += bias4.z; t.w += bias4.w;
            if (addb) {
                float4 ad = ((const float4*)addb)[gr_ * 32 + lane];
                t.x += ad.x; t.y += ad.y; t.z += ad.z; t.w += ad.w;
            }
            float4 s;
            s.x = t.x / (1.f + expf(-t.x));
            s.y = t.y / (1.f + expf(-t.y));
            s.z = t.z / (1.f + expf(-t.z));
            s.w = t.w / (1.f + expf(-t.w));
            float sum = s.x + s.y + s.z + s.w;
            float sq  = s.x * s.x + s.y * s.y + s.z * s.z + s.w * s.w;
#pragma unroll
            for (int off = 16; off; off >>= 1) {
                sum += __shfl_xor_sync(0xFFFFFFFFu, sum, off);
                sq  += __shfl_xor_sync(0xFFFFFFFFu, sq,  off);
            }
            const float mean = sum * (1.f / 128.f);
            const float var  = sq * (1.f / 128.f) - mean * mean;
            const float rstd = rsqrtf(var + EPSF);
            float4 o;
            o.x = (s.x - mean) * rstd * g4.x + b4.x;
            o.y = (s.y - mean) * rstd * g4.y + b4.y;
            o.z = (s.z - mean) * rstd * g4.z + b4.z;
            o.w = (s.w - mean) * rstd * g4.w + b4.w;
            ((float4*)C)[gr_ * 32 + lane] = o;
        }
    } else {
#pragma unroll
        for (int i = 0; i < 8; i++) {
            const int r = wid * 8 + i;
            const size_t gr_ = (size_t)blockRow + r;
            float4 t = *(const float4*)(Cs + r * AST + lane * 4);
            t.x += bias4.x; t.y += bias4.y; t.z += bias4.z; t.w += bias4.w;
            ((float4*)C)[gr_ * 32 + lane] = t;
        }
    }
}

// ---------------- k/q retention weights (fp32, exact) ----------------
__global__ void kq_kernel(const float* __restrict__ x,
                          const float* __restrict__ Wk, const float* __restrict__ Wq,
                          float* __restrict__ w0)
{
    __shared__ float4 sk4[KDIM * 32];
    __shared__ float4 sq4[KDIM * 32];
    float* sk = (float*)sk4;
    float* sqm = (float*)sq4;
    for (int idx = threadIdx.x; idx < DDIM * KDIM; idx += blockDim.x) {
        int k = idx >> 4, j = idx & 15;
        sk[j * DDIM + k] = Wk[idx];
        sqm[j * DDIM + k] = Wq[idx];
    }
    __syncthreads();

    const int lane = threadIdx.x & 31;
    int warp = (blockIdx.x * blockDim.x + threadIdx.x) >> 5;
    const int nwarps = (gridDim.x * blockDim.x) >> 5;

    for (size_t r = warp; r < (size_t)MROWS; r += nwarps) {
        const float4 xv = ((const float4*)x)[r * 32 + lane];
        float pk[KDIM], pq[KDIM];
#pragma unroll
        for (int j = 0; j < KDIM; j++) {
            float4 wk = sk4[j * 32 + lane];
            float4 wq = sq4[j * 32 + lane];
            pk[j] = xv.x * wk.x + xv.y * wk.y + xv.z * wk.z + xv.w * wk.w;
            pq[j] = xv.x * wq.x + xv.y * wq.y + xv.z * wq.z + xv.w * wq.w;
        }
#pragma unroll
        for (int off = 16; off; off >>= 1) {
#pragma unroll
            for (int j = 0; j < KDIM; j++) {
                pk[j] += __shfl_xor_sync(0xFFFFFFFFu, pk[j], off);
                pq[j] += __shfl_xor_sync(0xFFFFFFFFu, pq[j], off);
            }
        }
        if (lane == 0) {
            float s = 0.f;
#pragma unroll
            for (int j = 0; j < KDIM; j++) s += pk[j] * pq[j];
            w0[r] = s * (1.f / (float)KDIM);
        }
    }
}

// ---------------- attention output: att = LN(v * (w0+it1+it2)) ----------------
__global__ void att_ln_kernel(const float* __restrict__ v,
                              const float* __restrict__ w0, const float* __restrict__ it1,
                              const float* __restrict__ it2,
                              const float* __restrict__ g, const float* __restrict__ b,
                              float* __restrict__ out)
{
    const int lane = threadIdx.x & 31;
    int warp = (blockIdx.x * blockDim.x + threadIdx.x) >> 5;
    const int nwarps = (gridDim.x * blockDim.x) >> 5;
    const float4 g4 = ((const float4*)g)[lane];
    const float4 b4 = ((const float4*)b)[lane];

    for (size_t r = warp; r < (size_t)MROWS; r += nwarps) {
        const float w = w0[r] + it1[r] + it2[r];
        float4 s = ((const float4*)v)[r * 32 + lane];
        s.x *= w; s.y *= w; s.z *= w; s.w *= w;
        float sum = s.x + s.y + s.z + s.w;
        float sq  = s.x * s.x + s.y * s.y + s.z * s.z + s.w * s.w;
#pragma unroll
        for (int off = 16; off; off >>= 1) {
            sum += __shfl_xor_sync(0xFFFFFFFFu, sum, off);
            sq  += __shfl_xor_sync(0xFFFFFFFFu, sq,  off);
        }
        const float mean = sum * (1.f / 128.f);
        const float var  = sq * (1.f / 128.f) - mean * mean;
        const float rstd = rsqrtf(var + EPSF);
        float4 o;
        o.x = (s.x - mean) * rstd * g4.x + b4.x;
        o.y = (s.y - mean) * rstd * g4.y + b4.y;
        o.z = (s.z - mean) * rstd * g4.z + b4.z;
        o.w = (s.w - mean) * rstd * g4.w + b4.w;
        ((float4*)out)[r * 32 + lane] = o;
    }
}

// ---------------- host ----------------
extern "C" void kernel_launch(void* const* d_in, const int* in_sizes, int n_in,
                              void* d_out, int out_size)
{
    const float* x          = (const float*)d_in[0];
    const int*   ei         = (const int*)  d_in[1];
    const float* ev         = (const float*)d_in[2];
    const float* sage_W     = (const float*)d_in[3];
    const float* sage_b     = (const float*)d_in[4];
    const float* sage_aggW  = (const float*)d_in[5];
    const float* sage_ln_g  = (const float*)d_in[6];
    const float* sage_ln_b  = (const float*)d_in[7];
    const float* att_Wk     = (const float*)d_in[8];
    const float* att_Wq     = (const float*)d_in[9];
    const float* att_Wv     = (const float*)d_in[10];
    const float* att_ln_g   = (const float*)d_in[11];
    const float* att_ln_b   = (const float*)d_in[12];
    const float* lin1_W     = (const float*)d_in[13];
    const float* lin1_b     = (const float*)d_in[14];
    const float* lin2_W     = (const float*)d_in[15];
    const float* lin2_b     = (const float*)d_in[16];
    const float* ln1_g      = (const float*)d_in[17];
    const float* ln1_b      = (const float*)d_in[18];
    const float* ln2_g      = (const float*)d_in[19];
    const float* ln2_b      = (const float*)d_in[20];
    float* out = (float*)d_out;

    float *proj, *v, *agg, *sage, *att, *h, *w0, *it1, *it2, *bt;
    cudaGetSymbolAddress((void**)&proj, g_proj);
    cudaGetSymbolAddress((void**)&v,    g_v);
    cudaGetSymbolAddress((void**)&agg,  g_agg);
    cudaGetSymbolAddress((void**)&sage, g_sage);
    cudaGetSymbolAddress((void**)&att,  g_att);
    cudaGetSymbolAddress((void**)&h,    g_h);
    cudaGetSymbolAddress((void**)&w0,   g_w0);
    cudaGetSymbolAddress((void**)&it1,  g_it1);
    cudaGetSymbolAddress((void**)&it2,  g_it2);
    cudaGetSymbolAddress((void**)&bt,   g_bt);

    int *cnt, *cur, *rowstart, *ecol;
    float *eval_;
    cudaGetSymbolAddress((void**)&cnt,      g_cnt);
    cudaGetSymbolAddress((void**)&cur,      g_cur);
    cudaGetSymbolAddress((void**)&rowstart, g_rowstart);
    cudaGetSymbolAddress((void**)&ecol,     g_ecol);
    cudaGetSymbolAddress((void**)&eval_,    g_eval);

    cudaFuncSetAttribute(pre_kernel,    cudaFuncAttributeMaxDynamicSharedMemorySize, GEMM_SMEM);
    cudaFuncSetAttribute(gemm_tc<1, 2>, cudaFuncAttributeMaxDynamicSharedMemorySize, GEMM_SMEM);
    cudaFuncSetAttribute(gemm_tc<2, 2>, cudaFuncAttributeMaxDynamicSharedMemorySize, GEMM_SMEM);

    const int gemmGrid = MROWS / 64; // 3125

    // ---- weight prep: bt[0]=sage_W bt[1]=att_Wv bt[2]=sage_aggW bt[3,4]=lin1 bt[5]=lin2
    SixPtr sp;
    sp.p[0] = sage_W; sp.p[1] = att_Wv; sp.p[2] = sage_aggW;
    sp.p[3] = lin1_W; sp.p[4] = lin1_W + DDIM * DDIM; sp.p[5] = lin2_W;
    {
        dim3 tg(4, 4, 6), tb(32, 8);
        transpose_kernel<<<tg, tb>>>(sp, bt);
    }

    // ---- CSR build ----
    cudaMemsetAsync(cnt, 0, NNODES * sizeof(int), 0);
    cudaMemsetAsync(cur, 0, NNODES * sizeof(int), 0);
    hist_kernel<<<(EEDGES + 255) / 256, 256>>>(ei, cnt);
    scan_kernel<<<1, 1024>>>(cnt, rowstart);
    scatter_kernel<<<(EEDGES + 255) / 256, 256>>>(ei, ev, rowstart, cur, ecol, eval_);

    // fused: proj + v — single read of x
    pre_kernel<<<gemmGrid, 256, GEMM_SMEM>>>(x, bt, sage_b, proj, v);

    // retention base weights (fp32 exact)
    kq_kernel<<<1480, 256>>>(x, att_Wk, att_Wq, w0);

    // graph aggregation
    spmm_gather<<<(NNODES * 4 * 32 + 255) / 256, 256>>>(rowstart, ecol, eval_, x, agg);

    // retention iterations
    ret_gather<<<(NNODES * 32 + 255) / 256, 256>>>(rowstart, ecol, eval_, w0, it1);
    ret_gather<<<(NNODES * 32 + 255) / 256, 256>>>(rowstart, ecol, eval_, it1, it2);

    // sage_out = LN(silu(proj + agg @ aggW))
    gemm_tc<1, 2><<<gemmGrid, 256, GEMM_SMEM>>>(agg, nullptr, bt + 2 * DDIM * DDIM,
                                                nullptr, proj, sage_ln_g, sage_ln_b, sage);
    // att_out = LN(v * weights)
    att_ln_kernel<<<1480, 256>>>(v, w0, it1, it2, att_ln_g, att_ln_b, att);

    // h = LN(silu(concat(sage,att) @ lin1_W + lin1_b))
    gemm_tc<2, 2><<<gemmGrid, 256, GEMM_SMEM>>>(sage, att, bt + 3 * DDIM * DDIM,
                                                lin1_b, nullptr, ln1_g, ln1_b, h);
    // out = LN(silu(h @ lin2_W + lin2_b + x))
    gemm_tc<1, 2><<<gemmGrid, 256, GEMM_SMEM>>>(h, nullptr, bt + 5 * DDIM * DDIM,
                                                lin2_b, x, ln2_g, ln2_b, out);
}

// round 11
// speedup vs baseline: 1.7189x; 1.0718x over previous
#include <cuda_runtime.h>
#include <math.h>

#define NNODES 50000
#define LDIM   4
#define DDIM   128
#define KDIM   16
#define EEDGES 800000
#define MROWS  (LDIM * NNODES)        // 200000, multiple of 64
#define DECAYF 0.7f
#define EPSF   1e-5f

// ---------------- scratch (device globals; no allocation) ----------------
__device__ float g_v   [MROWS * DDIM];
__device__ float g_agg [MROWS * DDIM];
__device__ float g_sage[MROWS * DDIM];
__device__ float g_h   [MROWS * DDIM];
__device__ float g_w0 [MROWS];
__device__ float g_it1[MROWS];
__device__ float g_it2[MROWS];
__device__ float g_bt [6 * DDIM * DDIM];   // transposed weights [n][k]

// CSR build scratch
__device__ int   g_cnt[NNODES];
__device__ int   g_cur[NNODES];
__device__ int   g_rowstart[NNODES + 1];
__device__ int   g_ecol[EEDGES];
__device__ float g_eval[EEDGES];

// ================= weight transpose (once per launch, tiny) =================
struct SixPtr { const float* p[6]; };

__global__ void transpose_kernel(SixPtr srcs, float* __restrict__ dst)
{
    __shared__ float tile[32][33];
    const int m = blockIdx.z;
    const float* src = srcs.p[m];
    float* d = dst + m * DDIM * DDIM;
    const int bx = blockIdx.x * 32;
    const int by = blockIdx.y * 32;
    const int tx = threadIdx.x, ty = threadIdx.y;
#pragma unroll
    for (int j = 0; j < 32; j += 8)
        tile[ty + j][tx] = src[(by + ty + j) * DDIM + bx + tx];
    __syncthreads();
#pragma unroll
    for (int j = 0; j < 32; j += 8)
        d[(bx + ty + j) * DDIM + by + tx] = tile[tx][ty + j];
}

// ================= CSR construction =================
__global__ void hist_kernel(const int* __restrict__ ei, int* __restrict__ cnt)
{
    int e = blockIdx.x * blockDim.x + threadIdx.x;
    if (e < EEDGES) atomicAdd(&cnt[ei[e]], 1);
}

__global__ void scan_kernel(const int* __restrict__ cnt, int* __restrict__ rowstart)
{
    const int T = 1024;
    __shared__ int partial[T];
    const int tid = threadIdx.x;
    const int chunk = (NNODES + T - 1) / T;
    const int base = tid * chunk;
    int s = 0;
    for (int i = 0; i < chunk; i++) {
        int idx = base + i;
        if (idx < NNODES) s += cnt[idx];
    }
    partial[tid] = s;
    __syncthreads();
    for (int off = 1; off < T; off <<= 1) {
        int v = (tid >= off) ? partial[tid - off] : 0;
        __syncthreads();
        partial[tid] += v;
        __syncthreads();
    }
    int run = (tid == 0) ? 0 : partial[tid - 1];
    for (int i = 0; i < chunk; i++) {
        int idx = base + i;
        if (idx < NNODES) { rowstart[idx] = run; run += cnt[idx]; }
    }
    if (tid == T - 1) rowstart[NNODES] = run;
}

__global__ void scatter_kernel(const int* __restrict__ ei, const float* __restrict__ ev,
                               const int* __restrict__ rowstart, int* __restrict__ cur,
                               int* __restrict__ ecol, float* __restrict__ eval_)
{
    int e = blockIdx.x * blockDim.x + threadIdx.x;
    if (e >= EEDGES) return;
    const int r = ei[e];
    const int pos = rowstart[r] + atomicAdd(&cur[r], 1);
    ecol[pos]  = ei[EEDGES + e];
    eval_[pos] = ev[e];
}

// ================= gather spmm (no atomics): warp per (row, l), unroll 4 =====
__global__ void __launch_bounds__(256) spmm_gather(
    const int* __restrict__ rowstart,
    const int* __restrict__ ecol, const float* __restrict__ eval_,
    const float* __restrict__ x, float* __restrict__ agg)
{
    const int gw = (blockIdx.x * blockDim.x + threadIdx.x) >> 5;
    const int lane = threadIdx.x & 31;
    const int row = gw >> 2;
    const int l   = gw & 3;
    if (row >= NNODES) return;

    const int s = rowstart[row];
    const int e = rowstart[row + 1];
    const float4* xl = (const float4*)x + (size_t)l * NNODES * 32;

    float4 acc = make_float4(0.f, 0.f, 0.f, 0.f);
    int i = s;
    for (; i + 4 <= e; i += 4) {
        const int   c0 = ecol[i],   c1 = ecol[i+1], c2 = ecol[i+2], c3 = ecol[i+3];
        const float v0 = eval_[i],  v1 = eval_[i+1], v2 = eval_[i+2], v3 = eval_[i+3];
        float4 x0 = xl[(size_t)c0 * 32 + lane];
        float4 x1 = xl[(size_t)c1 * 32 + lane];
        float4 x2 = xl[(size_t)c2 * 32 + lane];
        float4 x3 = xl[(size_t)c3 * 32 + lane];
        acc.x += v0 * x0.x; acc.y += v0 * x0.y; acc.z += v0 * x0.z; acc.w += v0 * x0.w;
        acc.x += v1 * x1.x; acc.y += v1 * x1.y; acc.z += v1 * x1.z; acc.w += v1 * x1.w;
        acc.x += v2 * x2.x; acc.y += v2 * x2.y; acc.z += v2 * x2.z; acc.w += v2 * x2.w;
        acc.x += v3 * x3.x; acc.y += v3 * x3.y; acc.z += v3 * x3.z; acc.w += v3 * x3.w;
    }
    for (; i < e; i++) {
        const int c0 = ecol[i];
        const float v0 = eval_[i];
        float4 x0 = xl[(size_t)c0 * 32 + lane];
        acc.x += v0 * x0.x; acc.y += v0 * x0.y; acc.z += v0 * x0.z; acc.w += v0 * x0.w;
    }
    ((float4*)agg)[((size_t)l * NNODES + row) * 32 + lane] = acc;
}

// ================= retention spmm on [L,N] weights (gather) =================
__global__ void __launch_bounds__(256) ret_gather(
    const int* __restrict__ rowstart,
    const int* __restrict__ ecol, const float* __restrict__ eval_,
    const float* __restrict__ src, float* __restrict__ dst)
{
    const int row = (blockIdx.x * blockDim.x + threadIdx.x) >> 5;
    const int lane = threadIdx.x & 31;
    if (row >= NNODES) return;
    const int s = rowstart[row];
    const int e = rowstart[row + 1];

    float a0 = 0.f, a1 = 0.f, a2 = 0.f, a3 = 0.f;
    for (int i = s + lane; i < e; i += 32) {
        const int c = ecol[i];
        const float v = DECAYF * eval_[i];
        a0 += v * src[c];
        a1 += v * src[NNODES + c];
        a2 += v * src[2 * NNODES + c];
        a3 += v * src[3 * NNODES + c];
    }
#pragma unroll
    for (int off = 16; off; off >>= 1) {
        a0 += __shfl_xor_sync(0xFFFFFFFFu, a0, off);
        a1 += __shfl_xor_sync(0xFFFFFFFFu, a1, off);
        a2 += __shfl_xor_sync(0xFFFFFFFFu, a2, off);
        a3 += __shfl_xor_sync(0xFFFFFFFFu, a3, off);
    }
    if (lane == 0) {
        dst[row]              = a0;
        dst[NNODES + row]     = a1;
        dst[2 * NNODES + row] = a2;
        dst[3 * NNODES + row] = a3;
    }
}

// ================= common MMA helpers =================
#define AST 132
#define BST 132
#define GEMM_SMEM ((64 * AST + 128 * BST) * 4)   // 101376 bytes

__device__ __forceinline__ unsigned f2tf(float f)
{
    unsigned u;
    asm("cvt.rna.tf32.f32 %0, %1;" : "=r"(u) : "f"(f));
    return u;
}

__device__ __forceinline__ void mma8(float* c, const unsigned* a, unsigned b0, unsigned b1)
{
    asm volatile(
        "mma.sync.aligned.m16n8k8.row.col.f32.tf32.tf32.f32 "
        "{%0,%1,%2,%3},{%4,%5,%6,%7},{%8,%9},{%0,%1,%2,%3};"
        : "+f"(c[0]), "+f"(c[1]), "+f"(c[2]), "+f"(c[3])
        : "r"(a[0]), "r"(a[1]), "r"(a[2]), "r"(a[3]), "r"(b0), "r"(b1));
}

#define LDSM4(r, addr) \
    asm volatile("ldmatrix.sync.aligned.m8n8.x4.shared.b16 {%0,%1,%2,%3}, [%4];" \
        : "=r"((r)[0]), "=r"((r)[1]), "=r"((r)[2]), "=r"((r)[3]) : "r"(addr))

// fill helpers (device-inlined): A-tile (64 rows) and B-tile (128x128 weights)
__device__ __forceinline__ void fillA(unsigned* As, const float* A, int blockRow, int tid)
{
    const float4* Ag = (const float4*)(A + (size_t)blockRow * DDIM);
#pragma unroll
    for (int f = 0; f < 8; f++) {
        int i4 = tid + f * 256;
        float4 t = Ag[i4];
        int e = i4 * 4;
        *(uint4*)(As + (e >> 7) * AST + (e & 127)) =
            make_uint4(f2tf(t.x), f2tf(t.y), f2tf(t.z), f2tf(t.w));
    }
}

__device__ __forceinline__ void fillB(unsigned* Bs, const float* Bt, int tid)
{
    const float4* Bg = (const float4*)Bt;
#pragma unroll
    for (int f = 0; f < 16; f++) {
        int i4 = tid + f * 256;
        float4 t = Bg[i4];
        int e = i4 * 4;
        *(uint4*)(Bs + (e >> 7) * BST + (e & 127)) =
            make_uint4(f2tf(t.x), f2tf(t.y), f2tf(t.z), f2tf(t.w));
    }
}

// the 16-step k-loop (ldmatrix + 8 mma) over current As/Bs
__device__ __forceinline__ void mma_loop(float acc[8][4], unsigned aAddr, unsigned bAddr)
{
#pragma unroll
    for (int k8 = 0; k8 < 16; k8++) {
        const unsigned ko = k8 * 32;
        unsigned af[4], bf[4][4];
        LDSM4(af, aAddr + ko);
        LDSM4(bf[0], bAddr + ko);
        LDSM4(bf[1], bAddr + 16 * BST * 4 + ko);
        LDSM4(bf[2], bAddr + 32 * BST * 4 + ko);
        LDSM4(bf[3], bAddr + 48 * BST * 4 + ko);
#pragma unroll
        for (int nt = 0; nt < 8; nt++)
            mma8(acc[nt], af, bf[nt >> 1][(nt & 1) * 2], bf[nt >> 1][(nt & 1) * 2 + 1]);
    }
}

// LN(silu(.)) epilogue over staged Cs, optional addb
__device__ __forceinline__ void ln_epilogue(
    const float* Cs, int blockRow, int wid, int lane,
    const float* bias, const float* addb,
    const float* lng, const float* lnb, float* C)
{
    float4 bias4 = make_float4(0.f, 0.f, 0.f, 0.f);
    if (bias) bias4 = ((const float4*)bias)[lane];
    const float4 g4 = ((const float4*)lng)[lane];
    const float4 b4 = ((const float4*)lnb)[lane];
#pragma unroll
    for (int i = 0; i < 8; i++) {
        const int r = wid * 8 + i;
        const size_t gr_ = (size_t)blockRow + r;
        float4 t = *(const float4*)(Cs + r * AST + lane * 4);
        t.x += bias4.x; t.y += bias4.y; t.z += bias4.z; t.w += bias4.w;
        if (addb) {
            float4 ad = ((const float4*)addb)[gr_ * 32 + lane];
            t.x += ad.x; t.y += ad.y; t.z += ad.z; t.w += ad.w;
        }
        float4 s;
        s.x = t.x / (1.f + expf(-t.x));
        s.y = t.y / (1.f + expf(-t.y));
        s.z = t.z / (1.f + expf(-t.z));
        s.w = t.w / (1.f + expf(-t.w));
        float sum = s.x + s.y + s.z + s.w;
        float sq  = s.x * s.x + s.y * s.y + s.z * s.z + s.w * s.w;
#pragma unroll
        for (int off = 16; off; off >>= 1) {
            sum += __shfl_xor_sync(0xFFFFFFFFu, sum, off);
            sq  += __shfl_xor_sync(0xFFFFFFFFu, sq,  off);
        }
        const float mean = sum * (1.f / 128.f);
        const float var  = sq * (1.f / 128.f) - mean * mean;
        const float rstd = rsqrtf(var + EPSF);
        float4 o;
        o.x = (s.x - mean) * rstd * g4.x + b4.x;
        o.y = (s.y - mean) * rstd * g4.y + b4.y;
        o.z = (s.z - mean) * rstd * g4.z + b4.z;
        o.w = (s.w - mean) * rstd * g4.w + b4.w;
        ((float4*)C)[gr_ * 32 + lane] = o;
    }
}

__device__ __forceinline__ void stage_acc(float* Cs, const float acc[8][4],
                                          int wr, int wc, int tg, int gr)
{
    const int r0 = wr * 16 + gr;
#pragma unroll
    for (int nt = 0; nt < 8; nt++) {
        const int c = wc * 64 + nt * 8 + 2 * tg;
        *(float2*)(Cs + r0 * AST + c)       = make_float2(acc[nt][0], acc[nt][1]);
        *(float2*)(Cs + (r0 + 8) * AST + c) = make_float2(acc[nt][2], acc[nt][3]);
    }
}

// ================= fused_front: v = x@Wv ; sage = LN(silu(x@W + b + agg@aggW)) =
// bt layout: [0]=sage_W [1]=att_Wv [2]=sage_aggW
__global__ void __launch_bounds__(256, 2) fused_front(
    const float* __restrict__ x, const float* __restrict__ agg,
    const float* __restrict__ bt, const float* __restrict__ sage_b,
    const float* __restrict__ lng, const float* __restrict__ lnb,
    float* __restrict__ v, float* __restrict__ sage)
{
    extern __shared__ unsigned smem_u[];
    unsigned* As = smem_u;
    unsigned* Bs = smem_u + 64 * AST;
    float* Cs = (float*)smem_u;

    const int tid  = threadIdx.x;
    const int lane = tid & 31;
    const int wid  = tid >> 5;
    const int wr   = wid & 3;
    const int wc   = wid >> 2;
    const int tg   = lane & 3;
    const int gr   = lane >> 2;
    const int blockRow = blockIdx.x * 64;

    const unsigned sbase = (unsigned)__cvta_generic_to_shared(smem_u);
    const unsigned aAddr = sbase +
        ((wr * 16 + (lane & 15)) * AST + (lane >> 4) * 4) * 4u;
    const unsigned bAddr = sbase + 64u * AST * 4u +
        ((wc * 64 + (lane >> 4) * 8 + (lane & 7)) * BST + ((lane >> 3) & 1) * 4) * 4u;

    float acc[8][4];

    // pass 1: v = x @ Wv
    fillA(As, x, blockRow, tid);
    fillB(Bs, bt + 1 * DDIM * DDIM, tid);
    __syncthreads();
#pragma unroll
    for (int i = 0; i < 8; i++)
#pragma unroll
        for (int j = 0; j < 4; j++) acc[i][j] = 0.f;
    mma_loop(acc, aAddr, bAddr);
    // store v directly from fragments
    {
        const int r0 = blockRow + wr * 16 + gr;
#pragma unroll
        for (int nt = 0; nt < 8; nt++) {
            const int c = wc * 64 + nt * 8 + 2 * tg;
            ((float2*)v)[(size_t)r0 * 64 + (c >> 1)]       = make_float2(acc[nt][0], acc[nt][1]);
            ((float2*)v)[(size_t)(r0 + 8) * 64 + (c >> 1)] = make_float2(acc[nt][2], acc[nt][3]);
        }
    }
    __syncthreads();

    // pass 2: acc = x @ sage_W   (As still holds x)
    fillB(Bs, bt + 0 * DDIM * DDIM, tid);
    __syncthreads();
#pragma unroll
    for (int i = 0; i < 8; i++)
#pragma unroll
        for (int j = 0; j < 4; j++) acc[i][j] = 0.f;
    mma_loop(acc, aAddr, bAddr);
    __syncthreads();

    // pass 3: acc += agg @ aggW
    fillA(As, agg, blockRow, tid);
    fillB(Bs, bt + 2 * DDIM * DDIM, tid);
    __syncthreads();
    mma_loop(acc, aAddr, bAddr);
    __syncthreads();

    // epilogue: sage = LN(silu(acc + sage_b))
    stage_acc(Cs, acc, wr, wc, tg, gr);
    __syncthreads();
    ln_epilogue(Cs, blockRow, wid, lane, sage_b, nullptr, lng, lnb, sage);
}

// ================= lin1 GEMM with fused att in chunk-1 A-fill ================
// h = LN(silu(sage @ W0 + att @ W1 + b)), att = LN(v * (w0+it1+it2)) computed on the fly
__global__ void __launch_bounds__(256, 2) gemm_lin1(
    const float* __restrict__ sage, const float* __restrict__ v,
    const float* __restrict__ w0, const float* __restrict__ it1,
    const float* __restrict__ it2,
    const float* __restrict__ attg, const float* __restrict__ attb,
    const float* __restrict__ bt01,
    const float* __restrict__ bias,
    const float* __restrict__ lng, const float* __restrict__ lnb,
    float* __restrict__ C)
{
    extern __shared__ unsigned smem_u[];
    unsigned* As = smem_u;
    unsigned* Bs = smem_u + 64 * AST;
    float* Cs = (float*)smem_u;

    const int tid  = threadIdx.x;
    const int lane = tid & 31;
    const int wid  = tid >> 5;
    const int wr   = wid & 3;
    const int wc   = wid >> 2;
    const int tg   = lane & 3;
    const int gr   = lane >> 2;
    const int blockRow = blockIdx.x * 64;

    const unsigned sbase = (unsigned)__cvta_generic_to_shared(smem_u);
    const unsigned aAddr = sbase +
        ((wr * 16 + (lane & 15)) * AST + (lane >> 4) * 4) * 4u;
    const unsigned bAddr = sbase + 64u * AST * 4u +
        ((wc * 64 + (lane >> 4) * 8 + (lane & 7)) * BST + ((lane >> 3) & 1) * 4) * 4u;

    float acc[8][4];
#pragma unroll
    for (int i = 0; i < 8; i++)
#pragma unroll
        for (int j = 0; j < 4; j++) acc[i][j] = 0.f;

    // chunk 0: sage (plain fill)
    fillA(As, sage, blockRow, tid);
    fillB(Bs, bt01, tid);
    __syncthreads();
    mma_loop(acc, aAddr, bAddr);
    __syncthreads();

    // chunk 1: att computed on the fly from v & retention weights
    {
        const float4 ag4 = ((const float4*)attg)[lane];
        const float4 ab4 = ((const float4*)attb)[lane];
        const float4* Vg = (const float4*)(v + (size_t)blockRow * DDIM);
#pragma unroll
        for (int f = 0; f < 8; f++) {
            int i4 = tid + f * 256;
            int row = i4 >> 5;          // warp-constant
            int g   = i4 & 31;          // == lane
            size_t gr_ = (size_t)blockRow + row;
            float4 s = Vg[i4];
            const float w = w0[gr_] + it1[gr_] + it2[gr_];
            s.x *= w; s.y *= w; s.z *= w; s.w *= w;
            float sum = s.x + s.y + s.z + s.w;
            float sq  = s.x * s.x + s.y * s.y + s.z * s.z + s.w * s.w;
#pragma unroll
            for (int off = 16; off; off >>= 1) {
                sum += __shfl_xor_sync(0xFFFFFFFFu, sum, off);
                sq  += __shfl_xor_sync(0xFFFFFFFFu, sq,  off);
            }
            const float mean = sum * (1.f / 128.f);
            const float var  = sq * (1.f / 128.f) - mean * mean;
            const float rstd = rsqrtf(var + EPSF);
            float4 o;
            o.x = (s.x - mean) * rstd * ag4.x + ab4.x;
            o.y = (s.y - mean) * rstd * ag4.y + ab4.y;
            o.z = (s.z - mean) * rstd * ag4.z + ab4.z;
            o.w = (s.w - mean) * rstd * ag4.w + ab4.w;
            *(uint4*)(As + row * AST + g * 4) =
                make_uint4(f2tf(o.x), f2tf(o.y), f2tf(o.z), f2tf(o.w));
        }
    }
    fillB(Bs, bt01 + DDIM * DDIM, tid);
    __syncthreads();
    mma_loop(acc, aAddr, bAddr);
    __syncthreads();

    stage_acc(Cs, acc, wr, wc, tg, gr);
    __syncthreads();
    ln_epilogue(Cs, blockRow, wid, lane, bias, nullptr, lng, lnb, C);
}

// ================= generic tf32 GEMM + LN epilogue (lin2) ====================
__global__ void __launch_bounds__(256, 2) gemm_tc(
    const float* __restrict__ A0, const float* __restrict__ Bt,
    const float* __restrict__ bias, const float* __restrict__ addb,
    const float* __restrict__ lng, const float* __restrict__ lnb,
    float* __restrict__ C)
{
    extern __shared__ unsigned smem_u[];
    unsigned* As = smem_u;
    unsigned* Bs = smem_u + 64 * AST;
    float* Cs = (float*)smem_u;

    const int tid  = threadIdx.x;
    const int lane = tid & 31;
    const int wid  = tid >> 5;
    const int wr   = wid & 3;
    const int wc   = wid >> 2;
    const int tg   = lane & 3;
    const int gr   = lane >> 2;
    const int blockRow = blockIdx.x * 64;

    const unsigned sbase = (unsigned)__cvta_generic_to_shared(smem_u);
    const unsigned aAddr = sbase +
        ((wr * 16 + (lane & 15)) * AST + (lane >> 4) * 4) * 4u;
    const unsigned bAddr = sbase + 64u * AST * 4u +
        ((wc * 64 + (lane >> 4) * 8 + (lane & 7)) * BST + ((lane >> 3) & 1) * 4) * 4u;

    float acc[8][4];
#pragma unroll
    for (int i = 0; i < 8; i++)
#pragma unroll
        for (int j = 0; j < 4; j++) acc[i][j] = 0.f;

    fillA(As, A0, blockRow, tid);
    fillB(Bs, Bt, tid);
    __syncthreads();
    mma_loop(acc, aAddr, bAddr);
    __syncthreads();

    stage_acc(Cs, acc, wr, wc, tg, gr);
    __syncthreads();
    ln_epilogue(Cs, blockRow, wid, lane, bias, addb, lng, lnb, C);
}

// ---------------- k/q retention weights (fp32, exact) ----------------
__global__ void kq_kernel(const float* __restrict__ x,
                          const float* __restrict__ Wk, const float* __restrict__ Wq,
                          float* __restrict__ w0)
{
    __shared__ float4 sk4[KDIM * 32];
    __shared__ float4 sq4[KDIM * 32];
    float* sk = (float*)sk4;
    float* sqm = (float*)sq4;
    for (int idx = threadIdx.x; idx < DDIM * KDIM; idx += blockDim.x) {
        int k = idx >> 4, j = idx & 15;
        sk[j * DDIM + k] = Wk[idx];
        sqm[j * DDIM + k] = Wq[idx];
    }
    __syncthreads();

    const int lane = threadIdx.x & 31;
    int warp = (blockIdx.x * blockDim.x + threadIdx.x) >> 5;
    const int nwarps = (gridDim.x * blockDim.x) >> 5;

    for (size_t r = warp; r < (size_t)MROWS; r += nwarps) {
        const float4 xv = ((const float4*)x)[r * 32 + lane];
        float pk[KDIM], pq[KDIM];
#pragma unroll
        for (int j = 0; j < KDIM; j++) {
            float4 wk = sk4[j * 32 + lane];
            float4 wq = sq4[j * 32 + lane];
            pk[j] = xv.x * wk.x + xv.y * wk.y + xv.z * wk.z + xv.w * wk.w;
            pq[j] = xv.x * wq.x + xv.y * wq.y + xv.z * wq.z + xv.w * wq.w;
        }
#pragma unroll
        for (int off = 16; off; off >>= 1) {
#pragma unroll
            for (int j = 0; j < KDIM; j++) {
                pk[j] += __shfl_xor_sync(0xFFFFFFFFu, pk[j], off);
                pq[j] += __shfl_xor_sync(0xFFFFFFFFu, pq[j], off);
            }
        }
        if (lane == 0) {
            float s = 0.f;
#pragma unroll
            for (int j = 0; j < KDIM; j++) s += pk[j] * pq[j];
            w0[r] = s * (1.f / (float)KDIM);
        }
    }
}

// ---------------- host ----------------
extern "C" void kernel_launch(void* const* d_in, const int* in_sizes, int n_in,
                              void* d_out, int out_size)
{
    const float* x          = (const float*)d_in[0];
    const int*   ei         = (const int*)  d_in[1];
    const float* ev         = (const float*)d_in[2];
    const float* sage_W     = (const float*)d_in[3];
    const float* sage_b     = (const float*)d_in[4];
    const float* sage_aggW  = (const float*)d_in[5];
    const float* sage_ln_g  = (const float*)d_in[6];
    const float* sage_ln_b  = (const float*)d_in[7];
    const float* att_Wk     = (const float*)d_in[8];
    const float* att_Wq     = (const float*)d_in[9];
    const float* att_Wv     = (const float*)d_in[10];
    const float* att_ln_g   = (const float*)d_in[11];
    const float* att_ln_b   = (const float*)d_in[12];
    const float* lin1_W     = (const float*)d_in[13];
    const float* lin1_b     = (const float*)d_in[14];
    const float* lin2_W     = (const float*)d_in[15];
    const float* lin2_b     = (const float*)d_in[16];
    const float* ln1_g      = (const float*)d_in[17];
    const float* ln1_b      = (const float*)d_in[18];
    const float* ln2_g      = (const float*)d_in[19];
    const float* ln2_b      = (const float*)d_in[20];
    float* out = (float*)d_out;

    float *v, *agg, *sage, *h, *w0, *it1, *it2, *bt;
    cudaGetSymbolAddress((void**)&v,    g_v);
    cudaGetSymbolAddress((void**)&agg,  g_agg);
    cudaGetSymbolAddress((void**)&sage, g_sage);
    cudaGetSymbolAddress((void**)&h,    g_h);
    cudaGetSymbolAddress((void**)&w0,   g_w0);
    cudaGetSymbolAddress((void**)&it1,  g_it1);
    cudaGetSymbolAddress((void**)&it2,  g_it2);
    cudaGetSymbolAddress((void**)&bt,   g_bt);

    int *cnt, *cur, *rowstart, *ecol;
    float *eval_;
    cudaGetSymbolAddress((void**)&cnt,      g_cnt);
    cudaGetSymbolAddress((void**)&cur,      g_cur);
    cudaGetSymbolAddress((void**)&rowstart, g_rowstart);
    cudaGetSymbolAddress((void**)&ecol,     g_ecol);
    cudaGetSymbolAddress((void**)&eval_,    g_eval);

    cudaFuncSetAttribute(fused_front, cudaFuncAttributeMaxDynamicSharedMemorySize, GEMM_SMEM);
    cudaFuncSetAttribute(gemm_lin1,   cudaFuncAttributeMaxDynamicSharedMemorySize, GEMM_SMEM);
    cudaFuncSetAttribute(gemm_tc,     cudaFuncAttributeMaxDynamicSharedMemorySize, GEMM_SMEM);

    const int gemmGrid = MROWS / 64; // 3125

    // ---- weight prep: bt[0]=sage_W bt[1]=att_Wv bt[2]=sage_aggW bt[3,4]=lin1 bt[5]=lin2
    SixPtr sp;
    sp.p[0] = sage_W; sp.p[1] = att_Wv; sp.p[2] = sage_aggW;
    sp.p[3] = lin1_W; sp.p[4] = lin1_W + DDIM * DDIM; sp.p[5] = lin2_W;
    {
        dim3 tg(4, 4, 6), tb(32, 8);
        transpose_kernel<<<tg, tb>>>(sp, bt);
    }

    // ---- CSR build ----
    cudaMemsetAsync(cnt, 0, NNODES * sizeof(int), 0);
    cudaMemsetAsync(cur, 0, NNODES * sizeof(int), 0);
    hist_kernel<<<(EEDGES + 255) / 256, 256>>>(ei, cnt);
    scan_kernel<<<1, 1024>>>(cnt, rowstart);
    scatter_kernel<<<(EEDGES + 255) / 256, 256>>>(ei, ev, rowstart, cur, ecol, eval_);

    // retention base weights (fp32 exact)
    kq_kernel<<<1480, 256>>>(x, att_Wk, att_Wq, w0);

    // graph aggregation
    spmm_gather<<<(NNODES * 4 * 32 + 255) / 256, 256>>>(rowstart, ecol, eval_, x, agg);

    // retention iterations
    ret_gather<<<(NNODES * 32 + 255) / 256, 256>>>(rowstart, ecol, eval_, w0, it1);
    ret_gather<<<(NNODES * 32 + 255) / 256, 256>>>(rowstart, ecol, eval_, it1, it2);

    // v = x@Wv ; sage = LN(silu(x@sage_W + sage_b + agg@aggW))
    fused_front<<<gemmGrid, 256, GEMM_SMEM>>>(x, agg, bt, sage_b,
                                              sage_ln_g, sage_ln_b, v, sage);

    // h = LN(silu(sage@W0 + att@W1 + b)), att computed on the fly
    gemm_lin1<<<gemmGrid, 256, GEMM_SMEM>>>(sage, v, w0, it1, it2,
                                            att_ln_g, att_ln_b,
                                            bt + 3 * DDIM * DDIM, lin1_b,
                                            ln1_g, ln1_b, h);

    // out = LN(silu(h @ lin2_W + lin2_b + x))
    gemm_tc<<<gemmGrid, 256, GEMM_SMEM>>>(h, bt + 5 * DDIM * DDIM,
                                          lin2_b, x, ln2_g, ln2_b, out);
}

// round 12
// speedup vs baseline: 1.7736x; 1.0318x over previous
#include <cuda_runtime.h>
#include <math.h>

#define NNODES 50000
#define LDIM   4
#define DDIM   128
#define KDIM   16
#define EEDGES 800000
#define MROWS  (LDIM * NNODES)        // 200000, multiple of 64
#define DECAYF 0.7f
#define EPSF   1e-5f

// ---------------- scratch (device globals; no allocation) ----------------
__device__ float g_v   [MROWS * DDIM];
__device__ float g_agg [MROWS * DDIM];
__device__ float g_sage[MROWS * DDIM];
__device__ float g_h   [MROWS * DDIM];
__device__ float g_w0 [MROWS];
__device__ float g_it1[MROWS];
__device__ float g_it2[MROWS];
__device__ unsigned g_bt[6 * DDIM * DDIM];   // transposed weights [n][k], tf32 bits

// CSR build scratch
__device__ int   g_cnt[NNODES];
__device__ int   g_cur[NNODES];
__device__ int   g_rowstart[NNODES + 1];
__device__ int   g_ecol[EEDGES];
__device__ float g_eval[EEDGES];

__device__ __forceinline__ unsigned f2tf(float f)
{
    unsigned u;
    asm("cvt.rna.tf32.f32 %0, %1;" : "=r"(u) : "f"(f));
    return u;
}

// ================= weight transpose + tf32 convert (once, tiny) ==============
struct SixPtr { const float* p[6]; };

__global__ void transpose_kernel(SixPtr srcs, unsigned* __restrict__ dst)
{
    __shared__ float tile[32][33];
    const int m = blockIdx.z;
    const float* src = srcs.p[m];
    unsigned* d = dst + m * DDIM * DDIM;
    const int bx = blockIdx.x * 32;
    const int by = blockIdx.y * 32;
    const int tx = threadIdx.x, ty = threadIdx.y;
#pragma unroll
    for (int j = 0; j < 32; j += 8)
        tile[ty + j][tx] = src[(by + ty + j) * DDIM + bx + tx];
    __syncthreads();
#pragma unroll
    for (int j = 0; j < 32; j += 8)
        d[(bx + ty + j) * DDIM + by + tx] = f2tf(tile[tx][ty + j]);
}

// ================= CSR construction =================
__global__ void hist_kernel(const int* __restrict__ ei, int* __restrict__ cnt)
{
    int e = blockIdx.x * blockDim.x + threadIdx.x;
    if (e < EEDGES) atomicAdd(&cnt[ei[e]], 1);
}

__global__ void scan_kernel(const int* __restrict__ cnt, int* __restrict__ rowstart)
{
    const int T = 1024;
    __shared__ int partial[T];
    const int tid = threadIdx.x;
    const int chunk = (NNODES + T - 1) / T;
    const int base = tid * chunk;
    int s = 0;
    for (int i = 0; i < chunk; i++) {
        int idx = base + i;
        if (idx < NNODES) s += cnt[idx];
    }
    partial[tid] = s;
    __syncthreads();
    for (int off = 1; off < T; off <<= 1) {
        int v = (tid >= off) ? partial[tid - off] : 0;
        __syncthreads();
        partial[tid] += v;
        __syncthreads();
    }
    int run = (tid == 0) ? 0 : partial[tid - 1];
    for (int i = 0; i < chunk; i++) {
        int idx = base + i;
        if (idx < NNODES) { rowstart[idx] = run; run += cnt[idx]; }
    }
    if (tid == T - 1) rowstart[NNODES] = run;
}

__global__ void scatter_kernel(const int* __restrict__ ei, const float* __restrict__ ev,
                               const int* __restrict__ rowstart, int* __restrict__ cur,
                               int* __restrict__ ecol, float* __restrict__ eval_)
{
    int e = blockIdx.x * blockDim.x + threadIdx.x;
    if (e >= EEDGES) return;
    const int r = ei[e];
    const int pos = rowstart[r] + atomicAdd(&cur[r], 1);
    ecol[pos]  = ei[EEDGES + e];
    eval_[pos] = ev[e];
}

// ================= gather spmm: l-major warp order (L2-blocked) ==============
__global__ void __launch_bounds__(256) spmm_gather(
    const int* __restrict__ rowstart,
    const int* __restrict__ ecol, const float* __restrict__ eval_,
    const float* __restrict__ x, float* __restrict__ agg)
{
    const int gw = (blockIdx.x * blockDim.x + threadIdx.x) >> 5;
    const int lane = threadIdx.x & 31;
    if (gw >= 4 * NNODES) return;
    const int l   = gw / NNODES;         // l-major: one 25.6MB slice hot at a time
    const int row = gw - l * NNODES;

    const int s = rowstart[row];
    const int e = rowstart[row + 1];
    const float4* xl = (const float4*)x + (size_t)l * NNODES * 32;

    float4 acc = make_float4(0.f, 0.f, 0.f, 0.f);
    int i = s;
    for (; i + 4 <= e; i += 4) {
        const int   c0 = ecol[i],   c1 = ecol[i+1], c2 = ecol[i+2], c3 = ecol[i+3];
        const float v0 = eval_[i],  v1 = eval_[i+1], v2 = eval_[i+2], v3 = eval_[i+3];
        float4 x0 = xl[(size_t)c0 * 32 + lane];
        float4 x1 = xl[(size_t)c1 * 32 + lane];
        float4 x2 = xl[(size_t)c2 * 32 + lane];
        float4 x3 = xl[(size_t)c3 * 32 + lane];
        acc.x += v0 * x0.x; acc.y += v0 * x0.y; acc.z += v0 * x0.z; acc.w += v0 * x0.w;
        acc.x += v1 * x1.x; acc.y += v1 * x1.y; acc.z += v1 * x1.z; acc.w += v1 * x1.w;
        acc.x += v2 * x2.x; acc.y += v2 * x2.y; acc.z += v2 * x2.z; acc.w += v2 * x2.w;
        acc.x += v3 * x3.x; acc.y += v3 * x3.y; acc.z += v3 * x3.z; acc.w += v3 * x3.w;
    }
    for (; i < e; i++) {
        const int c0 = ecol[i];
        const float v0 = eval_[i];
        float4 x0 = xl[(size_t)c0 * 32 + lane];
        acc.x += v0 * x0.x; acc.y += v0 * x0.y; acc.z += v0 * x0.z; acc.w += v0 * x0.w;
    }
    ((float4*)agg)[((size_t)l * NNODES + row) * 32 + lane] = acc;
}

// ================= retention spmm on [L,N] weights (gather) =================
__global__ void __launch_bounds__(256) ret_gather(
    const int* __restrict__ rowstart,
    const int* __restrict__ ecol, const float* __restrict__ eval_,
    const float* __restrict__ src, float* __restrict__ dst)
{
    const int row = (blockIdx.x * blockDim.x + threadIdx.x) >> 5;
    const int lane = threadIdx.x & 31;
    if (row >= NNODES) return;
    const int s = rowstart[row];
    const int e = rowstart[row + 1];

    float a0 = 0.f, a1 = 0.f, a2 = 0.f, a3 = 0.f;
    for (int i = s + lane; i < e; i += 32) {
        const int c = ecol[i];
        const float v = DECAYF * eval_[i];
        a0 += v * src[c];
        a1 += v * src[NNODES + c];
        a2 += v * src[2 * NNODES + c];
        a3 += v * src[3 * NNODES + c];
    }
#pragma unroll
    for (int off = 16; off; off >>= 1) {
        a0 += __shfl_xor_sync(0xFFFFFFFFu, a0, off);
        a1 += __shfl_xor_sync(0xFFFFFFFFu, a1, off);
        a2 += __shfl_xor_sync(0xFFFFFFFFu, a2, off);
        a3 += __shfl_xor_sync(0xFFFFFFFFu, a3, off);
    }
    if (lane == 0) {
        dst[row]              = a0;
        dst[NNODES + row]     = a1;
        dst[2 * NNODES + row] = a2;
        dst[3 * NNODES + row] = a3;
    }
}

// ================= common MMA helpers =================
#define AST 132
#define BST 132
#define GEMM_SMEM ((64 * AST + 128 * BST) * 4)   // 101376 bytes

__device__ __forceinline__ void mma8(float* c, const unsigned* a, unsigned b0, unsigned b1)
{
    asm volatile(
        "mma.sync.aligned.m16n8k8.row.col.f32.tf32.tf32.f32 "
        "{%0,%1,%2,%3},{%4,%5,%6,%7},{%8,%9},{%0,%1,%2,%3};"
        : "+f"(c[0]), "+f"(c[1]), "+f"(c[2]), "+f"(c[3])
        : "r"(a[0]), "r"(a[1]), "r"(a[2]), "r"(a[3]), "r"(b0), "r"(b1));
}

#define LDSM4(r, addr) \
    asm volatile("ldmatrix.sync.aligned.m8n8.x4.shared.b16 {%0,%1,%2,%3}, [%4];" \
        : "=r"((r)[0]), "=r"((r)[1]), "=r"((r)[2]), "=r"((r)[3]) : "r"(addr))

// A-tile fill: fp32 -> tf32 convert
__device__ __forceinline__ void fillA(unsigned* As, const float* A, int blockRow, int tid)
{
    const float4* Ag = (const float4*)(A + (size_t)blockRow * DDIM);
#pragma unroll
    for (int f = 0; f < 8; f++) {
        int i4 = tid + f * 256;
        float4 t = Ag[i4];
        int e = i4 * 4;
        *(uint4*)(As + (e >> 7) * AST + (e & 127)) =
            make_uint4(f2tf(t.x), f2tf(t.y), f2tf(t.z), f2tf(t.w));
    }
}

// B-tile fill: weights pre-converted to tf32 bits — raw copy
__device__ __forceinline__ void fillB(unsigned* Bs, const unsigned* Bt, int tid)
{
    const uint4* Bg = (const uint4*)Bt;
#pragma unroll
    for (int f = 0; f < 16; f++) {
        int i4 = tid + f * 256;
        uint4 t = Bg[i4];
        int e = i4 * 4;
        *(uint4*)(Bs + (e >> 7) * BST + (e & 127)) = t;
    }
}

__device__ __forceinline__ void mma_loop(float acc[8][4], unsigned aAddr, unsigned bAddr)
{
#pragma unroll
    for (int k8 = 0; k8 < 16; k8++) {
        const unsigned ko = k8 * 32;
        unsigned af[4], bf[4][4];
        LDSM4(af, aAddr + ko);
        LDSM4(bf[0], bAddr + ko);
        LDSM4(bf[1], bAddr + 16 * BST * 4 + ko);
        LDSM4(bf[2], bAddr + 32 * BST * 4 + ko);
        LDSM4(bf[3], bAddr + 48 * BST * 4 + ko);
#pragma unroll
        for (int nt = 0; nt < 8; nt++)
            mma8(acc[nt], af, bf[nt >> 1][(nt & 1) * 2], bf[nt >> 1][(nt & 1) * 2 + 1]);
    }
}

__device__ __forceinline__ void ln_epilogue(
    const float* Cs, int blockRow, int wid, int lane,
    const float* bias, const float* addb,
    const float* lng, const float* lnb, float* C)
{
    float4 bias4 = make_float4(0.f, 0.f, 0.f, 0.f);
    if (bias) bias4 = ((const float4*)bias)[lane];
    const float4 g4 = ((const float4*)lng)[lane];
    const float4 b4 = ((const float4*)lnb)[lane];
#pragma unroll
    for (int i = 0; i < 8; i++) {
        const int r = wid * 8 + i;
        const size_t gr_ = (size_t)blockRow + r;
        float4 t = *(const float4*)(Cs + r * AST + lane * 4);
        t.x += bias4.x; t.y += bias4.y; t.z += bias4.z; t.w += bias4.w;
        if (addb) {
            float4 ad = ((const float4*)addb)[gr_ * 32 + lane];
            t.x += ad.x; t.y += ad.y; t.z += ad.z; t.w += ad.w;
        }
        float4 s;
        s.x = t.x / (1.f + expf(-t.x));
        s.y = t.y / (1.f + expf(-t.y));
        s.z = t.z / (1.f + expf(-t.z));
        s.w = t.w / (1.f + expf(-t.w));
        float sum = s.x + s.y + s.z + s.w;
        float sq  = s.x * s.x + s.y * s.y + s.z * s.z + s.w * s.w;
#pragma unroll
        for (int off = 16; off; off >>= 1) {
            sum += __shfl_xor_sync(0xFFFFFFFFu, sum, off);
            sq  += __shfl_xor_sync(0xFFFFFFFFu, sq,  off);
        }
        const float mean = sum * (1.f / 128.f);
        const float var  = sq * (1.f / 128.f) - mean * mean;
        const float rstd = rsqrtf(var + EPSF);
        float4 o;
        o.x = (s.x - mean) * rstd * g4.x + b4.x;
        o.y = (s.y - mean) * rstd * g4.y + b4.y;
        o.z = (s.z - mean) * rstd * g4.z + b4.z;
        o.w = (s.w - mean) * rstd * g4.w + b4.w;
        ((float4*)C)[gr_ * 32 + lane] = o;
    }
}

__device__ __forceinline__ void stage_acc(float* Cs, const float acc[8][4],
                                          int wr, int wc, int tg, int gr)
{
    const int r0 = wr * 16 + gr;
#pragma unroll
    for (int nt = 0; nt < 8; nt++) {
        const int c = wc * 64 + nt * 8 + 2 * tg;
        *(float2*)(Cs + r0 * AST + c)       = make_float2(acc[nt][0], acc[nt][1]);
        *(float2*)(Cs + (r0 + 8) * AST + c) = make_float2(acc[nt][2], acc[nt][3]);
    }
}

// ================= fused_front: v = x@Wv ; sage = LN(silu(x@W + b + agg@aggW)) =
__global__ void __launch_bounds__(256, 2) fused_front(
    const float* __restrict__ x, const float* __restrict__ agg,
    const unsigned* __restrict__ bt, const float* __restrict__ sage_b,
    const float* __restrict__ lng, const float* __restrict__ lnb,
    float* __restrict__ v, float* __restrict__ sage)
{
    extern __shared__ unsigned smem_u[];
    unsigned* As = smem_u;
    unsigned* Bs = smem_u + 64 * AST;
    float* Cs = (float*)smem_u;

    const int tid  = threadIdx.x;
    const int lane = tid & 31;
    const int wid  = tid >> 5;
    const int wr   = wid & 3;
    const int wc   = wid >> 2;
    const int tg   = lane & 3;
    const int gr   = lane >> 2;
    const int blockRow = blockIdx.x * 64;

    const unsigned sbase = (unsigned)__cvta_generic_to_shared(smem_u);
    const unsigned aAddr = sbase +
        ((wr * 16 + (lane & 15)) * AST + (lane >> 4) * 4) * 4u;
    const unsigned bAddr = sbase + 64u * AST * 4u +
        ((wc * 64 + (lane >> 4) * 8 + (lane & 7)) * BST + ((lane >> 3) & 1) * 4) * 4u;

    float acc[8][4];

    // pass 1: v = x @ Wv
    fillA(As, x, blockRow, tid);
    fillB(Bs, bt + 1 * DDIM * DDIM, tid);
    __syncthreads();
#pragma unroll
    for (int i = 0; i < 8; i++)
#pragma unroll
        for (int j = 0; j < 4; j++) acc[i][j] = 0.f;
    mma_loop(acc, aAddr, bAddr);
    {
        const int r0 = blockRow + wr * 16 + gr;
#pragma unroll
        for (int nt = 0; nt < 8; nt++) {
            const int c = wc * 64 + nt * 8 + 2 * tg;
            ((float2*)v)[(size_t)r0 * 64 + (c >> 1)]       = make_float2(acc[nt][0], acc[nt][1]);
            ((float2*)v)[(size_t)(r0 + 8) * 64 + (c >> 1)] = make_float2(acc[nt][2], acc[nt][3]);
        }
    }
    __syncthreads();

    // pass 2: acc = x @ sage_W   (As still holds x)
    fillB(Bs, bt + 0 * DDIM * DDIM, tid);
    __syncthreads();
#pragma unroll
    for (int i = 0; i < 8; i++)
#pragma unroll
        for (int j = 0; j < 4; j++) acc[i][j] = 0.f;
    mma_loop(acc, aAddr, bAddr);
    __syncthreads();

    // pass 3: acc += agg @ aggW
    fillA(As, agg, blockRow, tid);
    fillB(Bs, bt + 2 * DDIM * DDIM, tid);
    __syncthreads();
    mma_loop(acc, aAddr, bAddr);
    __syncthreads();

    stage_acc(Cs, acc, wr, wc, tg, gr);
    __syncthreads();
    ln_epilogue(Cs, blockRow, wid, lane, sage_b, nullptr, lng, lnb, sage);
}

// ================= lin1 GEMM with fused att in chunk-1 A-fill ================
__global__ void __launch_bounds__(256, 2) gemm_lin1(
    const float* __restrict__ sage, const float* __restrict__ v,
    const float* __restrict__ w0, const float* __restrict__ it1,
    const float* __restrict__ it2,
    const float* __restrict__ attg, const float* __restrict__ attb,
    const unsigned* __restrict__ bt01,
    const float* __restrict__ bias,
    const float* __restrict__ lng, const float* __restrict__ lnb,
    float* __restrict__ C)
{
    extern __shared__ unsigned smem_u[];
    unsigned* As = smem_u;
    unsigned* Bs = smem_u + 64 * AST;
    float* Cs = (float*)smem_u;

    const int tid  = threadIdx.x;
    const int lane = tid & 31;
    const int wid  = tid >> 5;
    const int wr   = wid & 3;
    const int wc   = wid >> 2;
    const int tg   = lane & 3;
    const int gr   = lane >> 2;
    const int blockRow = blockIdx.x * 64;

    const unsigned sbase = (unsigned)__cvta_generic_to_shared(smem_u);
    const unsigned aAddr = sbase +
        ((wr * 16 + (lane & 15)) * AST + (lane >> 4) * 4) * 4u;
    const unsigned bAddr = sbase + 64u * AST * 4u +
        ((wc * 64 + (lane >> 4) * 8 + (lane & 7)) * BST + ((lane >> 3) & 1) * 4) * 4u;

    float acc[8][4];
#pragma unroll
    for (int i = 0; i < 8; i++)
#pragma unroll
        for (int j = 0; j < 4; j++) acc[i][j] = 0.f;

    // chunk 0: sage
    fillA(As, sage, blockRow, tid);
    fillB(Bs, bt01, tid);
    __syncthreads();
    mma_loop(acc, aAddr, bAddr);
    __syncthreads();

    // chunk 1: att on the fly
    {
        const float4 ag4 = ((const float4*)attg)[lane];
        const float4 ab4 = ((const float4*)attb)[lane];
        const float4* Vg = (const float4*)(v + (size_t)blockRow * DDIM);
#pragma unroll
        for (int f = 0; f < 8; f++) {
            int i4 = tid + f * 256;
            int row = i4 >> 5;
            int g   = i4 & 31;
            size_t gr_ = (size_t)blockRow + row;
            float4 s = Vg[i4];
            const float w = w0[gr_] + it1[gr_] + it2[gr_];
            s.x *= w; s.y *= w; s.z *= w; s.w *= w;
            float sum = s.x + s.y + s.z + s.w;
            float sq  = s.x * s.x + s.y * s.y + s.z * s.z + s.w * s.w;
#pragma unroll
            for (int off = 16; off; off >>= 1) {
                sum += __shfl_xor_sync(0xFFFFFFFFu, sum, off);
                sq  += __shfl_xor_sync(0xFFFFFFFFu, sq,  off);
            }
            const float mean = sum * (1.f / 128.f);
            const float var  = sq * (1.f / 128.f) - mean * mean;
            const float rstd = rsqrtf(var + EPSF);
            float4 o;
            o.x = (s.x - mean) * rstd * ag4.x + ab4.x;
            o.y = (s.y - mean) * rstd * ag4.y + ab4.y;
            o.z = (s.z - mean) * rstd * ag4.z + ab4.z;
            o.w = (s.w - mean) * rstd * ag4.w + ab4.w;
            *(uint4*)(As + row * AST + g * 4) =
                make_uint4(f2tf(o.x), f2tf(o.y), f2tf(o.z), f2tf(o.w));
        }
    }
    fillB(Bs, bt01 + DDIM * DDIM, tid);
    __syncthreads();
    mma_loop(acc, aAddr, bAddr);
    __syncthreads();

    stage_acc(Cs, acc, wr, wc, tg, gr);
    __syncthreads();
    ln_epilogue(Cs, blockRow, wid, lane, bias, nullptr, lng, lnb, C);
}

// ================= generic tf32 GEMM + LN epilogue (lin2) ====================
__global__ void __launch_bounds__(256, 2) gemm_tc(
    const float* __restrict__ A0, const unsigned* __restrict__ Bt,
    const float* __restrict__ bias, const float* __restrict__ addb,
    const float* __restrict__ lng, const float* __restrict__ lnb,
    float* __restrict__ C)
{
    extern __shared__ unsigned smem_u[];
    unsigned* As = smem_u;
    unsigned* Bs = smem_u + 64 * AST;
    float* Cs = (float*)smem_u;

    const int tid  = threadIdx.x;
    const int lane = tid & 31;
    const int wid  = tid >> 5;
    const int wr   = wid & 3;
    const int wc   = wid >> 2;
    const int tg   = lane & 3;
    const int gr   = lane >> 2;
    const int blockRow = blockIdx.x * 64;

    const unsigned sbase = (unsigned)__cvta_generic_to_shared(smem_u);
    const unsigned aAddr = sbase +
        ((wr * 16 + (lane & 15)) * AST + (lane >> 4) * 4) * 4u;
    const unsigned bAddr = sbase + 64u * AST * 4u +
        ((wc * 64 + (lane >> 4) * 8 + (lane & 7)) * BST + ((lane >> 3) & 1) * 4) * 4u;

    float acc[8][4];
#pragma unroll
    for (int i = 0; i < 8; i++)
#pragma unroll
        for (int j = 0; j < 4; j++) acc[i][j] = 0.f;

    fillA(As, A0, blockRow, tid);
    fillB(Bs, Bt, tid);
    __syncthreads();
    mma_loop(acc, aAddr, bAddr);
    __syncthreads();

    stage_acc(Cs, acc, wr, wc, tg, gr);
    __syncthreads();
    ln_epilogue(Cs, blockRow, wid, lane, bias, addb, lng, lnb, C);
}

// ---------------- k/q retention weights (fp32, exact) ----------------
__global__ void kq_kernel(const float* __restrict__ x,
                          const float* __restrict__ Wk, const float* __restrict__ Wq,
                          float* __restrict__ w0)
{
    __shared__ float4 sk4[KDIM * 32];
    __shared__ float4 sq4[KDIM * 32];
    float* sk = (float*)sk4;
    float* sqm = (float*)sq4;
    for (int idx = threadIdx.x; idx < DDIM * KDIM; idx += blockDim.x) {
        int k = idx >> 4, j = idx & 15;
        sk[j * DDIM + k] = Wk[idx];
        sqm[j * DDIM + k] = Wq[idx];
    }
    __syncthreads();

    const int lane = threadIdx.x & 31;
    int warp = (blockIdx.x * blockDim.x + threadIdx.x) >> 5;
    const int nwarps = (gridDim.x * blockDim.x) >> 5;

    for (size_t r = warp; r < (size_t)MROWS; r += nwarps) {
        const float4 xv = ((const float4*)x)[r * 32 + lane];
        float pk[KDIM], pq[KDIM];
#pragma unroll
        for (int j = 0; j < KDIM; j++) {
            float4 wk = sk4[j * 32 + lane];
            float4 wq = sq4[j * 32 + lane];
            pk[j] = xv.x * wk.x + xv.y * wk.y + xv.z * wk.z + xv.w * wk.w;
            pq[j] = xv.x * wq.x + xv.y * wq.y + xv.z * wq.z + xv.w * wq.w;
        }
#pragma unroll
        for (int off = 16; off; off >>= 1) {
#pragma unroll
            for (int j = 0; j < KDIM; j++) {
                pk[j] += __shfl_xor_sync(0xFFFFFFFFu, pk[j], off);
                pq[j] += __shfl_xor_sync(0xFFFFFFFFu, pq[j], off);
            }
        }
        if (lane == 0) {
            float s = 0.f;
#pragma unroll
            for (int j = 0; j < KDIM; j++) s += pk[j] * pq[j];
            w0[r] = s * (1.f / (float)KDIM);
        }
    }
}

// ---------------- host ----------------
extern "C" void kernel_launch(void* const* d_in, const int* in_sizes, int n_in,
                              void* d_out, int out_size)
{
    const float* x          = (const float*)d_in[0];
    const int*   ei         = (const int*)  d_in[1];
    const float* ev         = (const float*)d_in[2];
    const float* sage_W     = (const float*)d_in[3];
    const float* sage_b     = (const float*)d_in[4];
    const float* sage_aggW  = (const float*)d_in[5];
    const float* sage_ln_g  = (const float*)d_in[6];
    const float* sage_ln_b  = (const float*)d_in[7];
    const float* att_Wk     = (const float*)d_in[8];
    const float* att_Wq     = (const float*)d_in[9];
    const float* att_Wv     = (const float*)d_in[10];
    const float* att_ln_g   = (const float*)d_in[11];
    const float* att_ln_b   = (const float*)d_in[12];
    const float* lin1_W     = (const float*)d_in[13];
    const float* lin1_b     = (const float*)d_in[14];
    const float* lin2_W     = (const float*)d_in[15];
    const float* lin2_b     = (const float*)d_in[16];
    const float* ln1_g      = (const float*)d_in[17];
    const float* ln1_b      = (const float*)d_in[18];
    const float* ln2_g      = (const float*)d_in[19];
    const float* ln2_b      = (const float*)d_in[20];
    float* out = (float*)d_out;

    float *v, *agg, *sage, *h, *w0, *it1, *it2;
    unsigned *bt;
    cudaGetSymbolAddress((void**)&v,    g_v);
    cudaGetSymbolAddress((void**)&agg,  g_agg);
    cudaGetSymbolAddress((void**)&sage, g_sage);
    cudaGetSymbolAddress((void**)&h,    g_h);
    cudaGetSymbolAddress((void**)&w0,   g_w0);
    cudaGetSymbolAddress((void**)&it1,  g_it1);
    cudaGetSymbolAddress((void**)&it2,  g_it2);
    cudaGetSymbolAddress((void**)&bt,   g_bt);

    int *cnt, *cur, *rowstart, *ecol;
    float *eval_;
    cudaGetSymbolAddress((void**)&cnt,      g_cnt);
    cudaGetSymbolAddress((void**)&cur,      g_cur);
    cudaGetSymbolAddress((void**)&rowstart, g_rowstart);
    cudaGetSymbolAddress((void**)&ecol,     g_ecol);
    cudaGetSymbolAddress((void**)&eval_,    g_eval);

    cudaFuncSetAttribute(fused_front, cudaFuncAttributeMaxDynamicSharedMemorySize, GEMM_SMEM);
    cudaFuncSetAttribute(gemm_lin1,   cudaFuncAttributeMaxDynamicSharedMemorySize, GEMM_SMEM);
    cudaFuncSetAttribute(gemm_tc,     cudaFuncAttributeMaxDynamicSharedMemorySize, GEMM_SMEM);

    const int gemmGrid = MROWS / 64; // 3125

    // ---- weight prep (transpose + tf32 convert) ----
    SixPtr sp;
    sp.p[0] = sage_W; sp.p[1] = att_Wv; sp.p[2] = sage_aggW;
    sp.p[3] = lin1_W; sp.p[4] = lin1_W + DDIM * DDIM; sp.p[5] = lin2_W;
    {
        dim3 tg(4, 4, 6), tb(32, 8);
        transpose_kernel<<<tg, tb>>>(sp, bt);
    }

    // ---- CSR build ----
    cudaMemsetAsync(cnt, 0, NNODES * sizeof(int), 0);
    cudaMemsetAsync(cur, 0, NNODES * sizeof(int), 0);
    hist_kernel<<<(EEDGES + 255) / 256, 256>>>(ei, cnt);
    scan_kernel<<<1, 1024>>>(cnt, rowstart);
    scatter_kernel<<<(EEDGES + 255) / 256, 256>>>(ei, ev, rowstart, cur, ecol, eval_);

    // retention base weights (fp32 exact)
    kq_kernel<<<1480, 256>>>(x, att_Wk, att_Wq, w0);

    // graph aggregation (l-major for L2 blocking)
    spmm_gather<<<(NNODES * 4 * 32 + 255) / 256, 256>>>(rowstart, ecol, eval_, x, agg);

    // retention iterations
    ret_gather<<<(NNODES * 32 + 255) / 256, 256>>>(rowstart, ecol, eval_, w0, it1);
    ret_gather<<<(NNODES * 32 + 255) / 256, 256>>>(rowstart, ecol, eval_, it1, it2);

    // v = x@Wv ; sage = LN(silu(x@sage_W + sage_b + agg@aggW))
    fused_front<<<gemmGrid, 256, GEMM_SMEM>>>(x, agg, bt, sage_b,
                                              sage_ln_g, sage_ln_b, v, sage);

    // h = LN(silu(sage@W0 + att@W1 + b)), att computed on the fly
    gemm_lin1<<<gemmGrid, 256, GEMM_SMEM>>>(sage, v, w0, it1, it2,
                                            att_ln_g, att_ln_b,
                                            bt + 3 * DDIM * DDIM, lin1_b,
                                            ln1_g, ln1_b, h);

    // out = LN(silu(h @ lin2_W + lin2_b + x))
    gemm_tc<<<gemmGrid, 256, GEMM_SMEM>>>(h, bt + 5 * DDIM * DDIM,
                                          lin2_b, x, ln2_g, ln2_b, out);
}